// round 13
// baseline (speedup 1.0000x reference)
#include <cuda_runtime.h>
#include <cuda_bf16.h>
#include <math.h>
#include <stdint.h>

// Problem constants
#define HH 16
#define DHH 64
static constexpr int Bc   = 2;
static constexpr int Nq   = 1024;
static constexpr int NCTX = 2048;
static constexpr int DIM  = 1024;
static constexpr int NMEM = 16;
static constexpr int JJ   = NCTX + NMEM;   // 2064
static constexpr int JJP  = 2080;          // padded to multiple of 32 (BK)
static constexpr int HDH  = HH * DHH;      // 1024

// ---------------- scratch (device globals) ----------------------------------
__device__ float g_qn[(size_t)Bc * HH * Nq * DHH];
__device__ float g_kn[(size_t)Bc * HH * JJ * DHH];
__device__ float g_dots[(size_t)Bc * HH * Nq * (size_t)JJ];
__device__ float g_scale[HH];

// pre-split bf16 operand arrays (hi / lo)
__device__ __align__(16) __nv_bfloat16 g_xH [(size_t)Bc * Nq * DIM];
__device__ __align__(16) __nv_bfloat16 g_xL [(size_t)Bc * Nq * DIM];
__device__ __align__(16) __nv_bfloat16 g_cH [(size_t)Bc * NCTX * DIM];
__device__ __align__(16) __nv_bfloat16 g_cL [(size_t)Bc * NCTX * DIM];
__device__ __align__(16) __nv_bfloat16 g_wTH[(size_t)HDH * DIM];
__device__ __align__(16) __nv_bfloat16 g_wTL[(size_t)HDH * DIM];
__device__ __align__(16) __nv_bfloat16 g_qnH[(size_t)Bc * HH * Nq * DHH];
__device__ __align__(16) __nv_bfloat16 g_qnL[(size_t)Bc * HH * Nq * DHH];
__device__ __align__(16) __nv_bfloat16 g_knH[(size_t)Bc * HH * JJ * DHH];
__device__ __align__(16) __nv_bfloat16 g_knL[(size_t)Bc * HH * JJ * DHH];
__device__ __align__(16) __nv_bfloat16 g_vTH[(size_t)Bc * HH * DHH * JJP];
__device__ __align__(16) __nv_bfloat16 g_vTL[(size_t)Bc * HH * DHH * JJP];
__device__ __align__(16) __nv_bfloat16 g_atH[(size_t)Bc * HH * Nq * JJP];
__device__ __align__(16) __nv_bfloat16 g_atL[(size_t)Bc * HH * Nq * JJP];
__device__ __align__(16) __nv_bfloat16 g_ctH[(size_t)Bc * Nq * HDH];
__device__ __align__(16) __nv_bfloat16 g_ctL[(size_t)Bc * Nq * HDH];

// ---------------- split helpers ---------------------------------------------
__device__ __forceinline__ uint32_t pack_bf2(__nv_bfloat16 a, __nv_bfloat16 b) {
    return ((uint32_t)__bfloat16_as_ushort(b) << 16) | (uint32_t)__bfloat16_as_ushort(a);
}
__device__ __forceinline__ void split_bf16(float x, __nv_bfloat16& h, __nv_bfloat16& l) {
    h = __float2bfloat16(x);
    l = __float2bfloat16(x - __bfloat162float(h));
}

// ---------------- tiny kernels ----------------------------------------------

__global__ void scale_kernel(float* __restrict__ out, const float* __restrict__ p) {
    int h = threadIdx.x;
    if (h < HH) out[h] = 1.0f / fmaxf(expf(p[h]), 0.01f);
}

// elementwise fp32 -> bf16 hi/lo split (float4 granularity)
__global__ void split_kernel(__nv_bfloat16* __restrict__ H, __nv_bfloat16* __restrict__ L,
                             const float* __restrict__ src, long n4) {
    long i = blockIdx.x * (long)blockDim.x + threadIdx.x;
    if (i >= n4) return;
    float4 v = reinterpret_cast<const float4*>(src)[i];
    __nv_bfloat16 h0,l0,h1,l1,h2,l2,h3,l3;
    split_bf16(v.x,h0,l0); split_bf16(v.y,h1,l1);
    split_bf16(v.z,h2,l2); split_bf16(v.w,h3,l3);
    uint2 hw = make_uint2(pack_bf2(h0,h1), pack_bf2(h2,h3));
    uint2 lw = make_uint2(pack_bf2(l0,l1), pack_bf2(l2,l3));
    reinterpret_cast<uint2*>(H)[i] = hw;
    reinterpret_cast<uint2*>(L)[i] = lw;
}

// transpose + split: src [K][N] fp32 -> dst[n][k] bf16 hi/lo
__global__ void tconv_kernel(__nv_bfloat16* __restrict__ H, __nv_bfloat16* __restrict__ L,
                             const float* __restrict__ src, int K, int N) {
    __shared__ float t[32][33];
    int n0 = blockIdx.x * 32, k0 = blockIdx.y * 32;
    for (int yy = threadIdx.y; yy < 32; yy += 8)
        t[yy][threadIdx.x] = src[(long)(k0 + yy) * N + n0 + threadIdx.x];
    __syncthreads();
    for (int yy = threadIdx.y; yy < 32; yy += 8) {
        float v = t[threadIdx.x][yy];                  // src[k0+tx][n0+yy]
        long o = (long)(n0 + yy) * K + k0 + threadIdx.x;
        __nv_bfloat16 h, l; split_bf16(v, h, l);
        H[o] = h; L[o] = l;
    }
}

// memory K rows (fp32, later l2norm'd) + memory V columns (split, transposed) + vT pad zero
__global__ void memfill_kernel(float* __restrict__ kn,
                               __nv_bfloat16* __restrict__ vTH, __nv_bfloat16* __restrict__ vTL,
                               const float* __restrict__ mk, const float* __restrict__ mv) {
    int idx = blockIdx.x * blockDim.x + threadIdx.x;
    const int total = HH * NMEM * DHH;   // 16384
    if (idx >= total) return;
    int h   = idx / (NMEM * DHH);
    int rem = idx % (NMEM * DHH);
    int m = rem / DHH, d = rem % DHH;
    float k = mk[idx], v = mv[idx];
    __nv_bfloat16 vh, vl; split_bf16(v, vh, vl);
    for (int b = 0; b < Bc; b++) {
        kn[(((size_t)(b * HH + h) * JJ) + m) * DHH + d] = k;
        size_t base = ((size_t)(b * HH + h) * DHH + d) * JJP;
        vTH[base + m] = vh;            vTL[base + m] = vl;
        vTH[base + JJ + m] = __float2bfloat16(0.f);   // zero pad cols [2064,2080)
        vTL[base + JJ + m] = __float2bfloat16(0.f);
    }
}

// l2-normalize rows of 64 fp32 and emit split bf16; one warp per row
__global__ void l2norm_split_kernel(const float* __restrict__ src,
                                    __nv_bfloat16* __restrict__ H,
                                    __nv_bfloat16* __restrict__ L, int rows) {
    int row = blockIdx.x * 8 + (threadIdx.x >> 5);
    if (row >= rows) return;
    int lane = threadIdx.x & 31;
    float2 v = reinterpret_cast<const float2*>(src + (size_t)row * DHH)[lane];
    float ss = v.x * v.x + v.y * v.y;
    #pragma unroll
    for (int o = 16; o; o >>= 1) ss += __shfl_xor_sync(0xffffffffu, ss, o);
    float inv = 1.0f / fmaxf(sqrtf(ss), 1e-12f);
    __nv_bfloat16 hx,lx,hy,ly;
    split_bf16(v.x * inv, hx, lx);
    split_bf16(v.y * inv, hy, ly);
    reinterpret_cast<uint32_t*>(H)[(size_t)row * 32 + lane] = pack_bf2(hx, hy);
    reinterpret_cast<uint32_t*>(L)[(size_t)row * 32 + lane] = pack_bf2(lx, ly);
}

// ---------------- fused talking-heads pre-mix + softmax + post-mix ----------
// reads dots fp32 (pitch JJ), writes attn split bf16 (pitch JJP, pads zeroed)
__global__ void mix_softmax_kernel(const float* __restrict__ dots,
                                   __nv_bfloat16* __restrict__ atH,
                                   __nv_bfloat16* __restrict__ atL,
                                   const float* __restrict__ th_pre,
                                   const float* __restrict__ th_post) {
    extern __shared__ float sh[];                 // [16][JJ]
    __shared__ float s_pre[HH * HH], s_post[HH * HH];
    __shared__ float red[HH][8];
    __shared__ float gmax[HH], gsum[HH], Mmat[HH * HH];

    const int bi = blockIdx.x;
    const int b = bi / Nq, i = bi % Nq;
    const int tid = threadIdx.x;                  // 256
    const int warp = tid >> 5, lane = tid & 31;

    s_pre[tid]  = th_pre[tid];
    s_post[tid] = th_post[tid];

    for (int h = 0; h < HH; h++) {
        const float* src = dots + (((size_t)(b * HH + h) * Nq + i) * JJ);
        for (int j = tid; j < JJ; j += 256) sh[h * JJ + j] = src[j];
    }
    __syncthreads();

    float lmax[HH];
    #pragma unroll
    for (int g = 0; g < HH; g++) lmax[g] = -1e30f;
    for (int j = tid; j < JJ; j += 256) {
        float d[HH];
        #pragma unroll
        for (int h = 0; h < HH; h++) d[h] = sh[h * JJ + j];
        #pragma unroll
        for (int g = 0; g < HH; g++) {
            float m = 0.0f;
            #pragma unroll
            for (int h = 0; h < HH; h++) m = fmaf(s_pre[g * HH + h], d[h], m);
            sh[g * JJ + j] = m;
            lmax[g] = fmaxf(lmax[g], m);
        }
    }
    __syncthreads();
    #pragma unroll
    for (int g = 0; g < HH; g++) {
        float v = lmax[g];
        #pragma unroll
        for (int o = 16; o; o >>= 1) v = fmaxf(v, __shfl_xor_sync(0xffffffffu, v, o));
        if (lane == 0) red[g][warp] = v;
    }
    __syncthreads();
    if (tid < HH) {
        float v = red[tid][0];
        #pragma unroll
        for (int w = 1; w < 8; w++) v = fmaxf(v, red[tid][w]);
        gmax[tid] = v;
    }
    __syncthreads();

    float lsum[HH];
    #pragma unroll
    for (int g = 0; g < HH; g++) lsum[g] = 0.0f;
    for (int j = tid; j < JJ; j += 256) {
        #pragma unroll
        for (int g = 0; g < HH; g++) {
            float e = __expf(sh[g * JJ + j] - gmax[g]);
            sh[g * JJ + j] = e;
            lsum[g] += e;
        }
    }
    __syncthreads();
    #pragma unroll
    for (int g = 0; g < HH; g++) {
        float v = lsum[g];
        #pragma unroll
        for (int o = 16; o; o >>= 1) v += __shfl_xor_sync(0xffffffffu, v, o);
        if (lane == 0) red[g][warp] = v;
    }
    __syncthreads();
    if (tid < HH) {
        float v = 0.0f;
        #pragma unroll
        for (int w = 0; w < 8; w++) v += red[tid][w];
        gsum[tid] = v;
    }
    __syncthreads();
    Mmat[tid] = s_post[tid] / gsum[tid & 15];
    __syncthreads();

    for (int j = tid; j < JJP; j += 256) {
        float e[HH];
        bool in = (j < JJ);
        #pragma unroll
        for (int h = 0; h < HH; h++) e[h] = in ? sh[h * JJ + j] : 0.0f;
        #pragma unroll
        for (int g = 0; g < HH; g++) {
            float o = 0.0f;
            #pragma unroll
            for (int h = 0; h < HH; h++) o = fmaf(Mmat[g * HH + h], e[h], o);
            size_t oi = (((size_t)(b * HH + g) * Nq + i) * JJP) + j;
            __nv_bfloat16 oh, ol; split_bf16(o, oh, ol);
            atH[oi] = oh; atL[oi] = ol;
        }
    }
}

// ---------------- pre-split bf16x2 GEMM with cp.async pipeline --------------
// A: [M][K] bf16 hi/lo row-major.  B: [Nc][K] bf16 hi/lo row-major (n-major).
// C = A @ B^T, fp32 accum via 3-term mma (loH + hiL + hiH). K % 32 == 0.

__device__ __forceinline__ void cp16(uint32_t dst, const void* src) {
    asm volatile("cp.async.ca.shared.global [%0], [%1], 16;" :: "r"(dst), "l"(src));
}
__device__ __forceinline__ void cpcommit() { asm volatile("cp.async.commit_group;"); }
template<int N> __device__ __forceinline__ void cpwait() {
    asm volatile("cp.async.wait_group %0;" :: "n"(N));
}

__device__ __forceinline__ void mma_bf16(float* c, const uint32_t* a, const uint32_t* b) {
    asm volatile(
        "mma.sync.aligned.m16n8k16.row.col.f32.bf16.bf16.f32 "
        "{%0,%1,%2,%3}, {%4,%5,%6,%7}, {%8,%9}, {%0,%1,%2,%3};"
        : "+f"(c[0]), "+f"(c[1]), "+f"(c[2]), "+f"(c[3])
        : "r"(a[0]), "r"(a[1]), "r"(a[2]), "r"(a[3]),
          "r"(b[0]), "r"(b[1]));
}

template<int BM, int BN, int WM, int WN, bool GUARDN>
__global__ void __launch_bounds__((BM / WM) * (BN / WN) * 32)
psgemm_kernel(
    int M, int Nc, int K,
    const __nv_bfloat16* __restrict__ AH, const __nv_bfloat16* __restrict__ AL,
    long lda, long sA,
    const __nv_bfloat16* __restrict__ BH, const __nv_bfloat16* __restrict__ BL,
    long ldb, long sB,
    void* C0, void* C1, long sC,
    const float* __restrict__ alphaVec,
    float beta, int mode, int p1, int p2, int p3)
{
    constexpr int BK  = 32;
    constexpr int NTH = (BM / WM) * (BN / WN) * 32;
    constexpr int PA  = BK / 2 + 4;          // 20 u32 words (80B, 16B-aligned)
    constexpr int AW  = BM * PA;             // words per A array
    constexpr int BW  = BN * PA;             // words per B array
    constexpr int SW  = 2 * AW + 2 * BW;     // words per stage
    constexpr int MFR = WM / 16;
    constexpr int NFR = WN / 8;

    extern __shared__ uint32_t smem[];
    const uint32_t smem_addr = (uint32_t)__cvta_generic_to_shared(smem);

    const int z = blockIdx.z;
    const __nv_bfloat16* Ah = AH + (long)z * sA;
    const __nv_bfloat16* Al = AL + (long)z * sA;
    const __nv_bfloat16* Bh = BH + (long)z * sB;
    const __nv_bfloat16* Bl = BL + (long)z * sB;

    const int tid  = threadIdx.x;
    const int warp = tid >> 5;
    const int lane = tid & 31;
    const int g    = lane >> 2;
    const int tg   = lane & 3;
    const int wr   = warp / (BN / WN);
    const int wc   = warp % (BN / WN);
    const int rowBase = blockIdx.y * BM;
    const int colBase = blockIdx.x * BN;

    float acc[MFR][NFR][4];
    #pragma unroll
    for (int i = 0; i < MFR; i++)
        #pragma unroll
        for (int j = 0; j < NFR; j++)
            #pragma unroll
            for (int q = 0; q < 4; q++) acc[i][j][q] = 0.0f;

    auto load_tile = [&](int stage, int k0) {
        uint32_t base = smem_addr + (uint32_t)stage * SW * 4;
        // A: BM rows x 4 chunks of 8 bf16
        #pragma unroll 2
        for (int idx = tid; idx < BM * 4; idx += NTH) {
            int r  = idx >> 2;
            int c8 = idx & 3;
            long go = (long)(rowBase + r) * lda + k0 + c8 * 8;
            uint32_t d = base + (uint32_t)(r * PA + c8 * 4) * 4;
            cp16(d, Ah + go);
            cp16(d + AW * 4, Al + go);
        }
        // B: BN rows x 4 chunks
        #pragma unroll 2
        for (int idx = tid; idx < BN * 4; idx += NTH) {
            int c  = idx >> 2;
            int k8 = idx & 3;
            int gc = colBase + c;
            uint32_t d = base + (uint32_t)(2 * AW + c * PA + k8 * 4) * 4;
            if (!GUARDN || gc < Nc) {
                long go = (long)gc * ldb + k0 + k8 * 8;
                cp16(d, Bh + go);
                cp16(d + BW * 4, Bl + go);
            } else {
                uint4 zz = make_uint4(0, 0, 0, 0);
                *reinterpret_cast<uint4*>(&smem[stage * SW + 2 * AW + c * PA + k8 * 4]) = zz;
                *reinterpret_cast<uint4*>(&smem[stage * SW + 2 * AW + BW + c * PA + k8 * 4]) = zz;
            }
        }
    };

    const int nK = K / BK;
    load_tile(0, 0);
    cpcommit();

    for (int kt = 0; kt < nK; kt++) {
        int cur = kt & 1;
        if (kt + 1 < nK) load_tile((kt + 1) & 1, (kt + 1) * BK);
        cpcommit();
        cpwait<1>();
        __syncthreads();

        const uint32_t* AsH = smem + cur * SW;
        const uint32_t* AsL = AsH + AW;
        const uint32_t* BsH = AsH + 2 * AW;
        const uint32_t* BsL = BsH + BW;

        #pragma unroll
        for (int kk = 0; kk < BK; kk += 16) {
            const int kp = kk / 2;
            uint32_t afH[MFR][4], afL[MFR][4];
            uint32_t bfH[NFR][2], bfL[NFR][2];
            #pragma unroll
            for (int mi = 0; mi < MFR; mi++) {
                int mrow = wr * WM + mi * 16 + g;
                int i00 = (mrow    ) * PA + kp + tg;
                int i10 = (mrow + 8) * PA + kp + tg;
                afH[mi][0] = AsH[i00];     afL[mi][0] = AsL[i00];
                afH[mi][1] = AsH[i10];     afL[mi][1] = AsL[i10];
                afH[mi][2] = AsH[i00 + 4]; afL[mi][2] = AsL[i00 + 4];
                afH[mi][3] = AsH[i10 + 4]; afL[mi][3] = AsL[i10 + 4];
            }
            #pragma unroll
            for (int ni = 0; ni < NFR; ni++) {
                int ncol = wc * WN + ni * 8 + g;
                int j0 = ncol * PA + kp + tg;
                bfH[ni][0] = BsH[j0];     bfL[ni][0] = BsL[j0];
                bfH[ni][1] = BsH[j0 + 4]; bfL[ni][1] = BsL[j0 + 4];
            }
            #pragma unroll
            for (int mi = 0; mi < MFR; mi++)
                #pragma unroll
                for (int ni = 0; ni < NFR; ni++) {
                    float* c = acc[mi][ni];
                    mma_bf16(c, afL[mi], bfH[ni]);
                    mma_bf16(c, afH[mi], bfL[ni]);
                    mma_bf16(c, afH[mi], bfH[ni]);
                }
        }
        __syncthreads();
    }

    float alpha = 1.0f;
    if (alphaVec) alpha = alphaVec[z % HH];

    #pragma unroll
    for (int mi = 0; mi < MFR; mi++) {
        #pragma unroll
        for (int half = 0; half < 2; half++) {
            int gr = rowBase + wr * WM + mi * 16 + g + half * 8;
            if (gr >= M) continue;
            #pragma unroll
            for (int ni = 0; ni < NFR; ni++) {
                #pragma unroll
                for (int e = 0; e < 2; e++) {
                    int gc = colBase + wc * WN + ni * 8 + tg * 2 + e;
                    if (gc >= Nc) continue;
                    float val = alpha * acc[mi][ni][half * 2 + e];
                    if (mode == 0) {                      // plain fp32 + beta
                        float* cp = (float*)C0 + (long)gr * p1 + gc;
                        *cp = (beta == 0.0f) ? val : fmaf(beta, *cp, val);
                    } else if (mode == 1) {               // split-heads fp32 (q/k)
                        int b = gr / p1;
                        int rr = gr - b * p1;
                        int h = gc >> 6, d = gc & 63;
                        ((float*)C0)[(((long)(b * HH + h) * p2 + p3 + rr) << 6) + d] = val;
                    } else if (mode == 2) {               // cat split bf16
                        int b = z >> 4, h = z & 15;
                        long oi = (((long)(b * p1 + gr) * HH + h) << 6) + gc;
                        __nv_bfloat16 vh, vl; split_bf16(val, vh, vl);
                        ((__nv_bfloat16*)C0)[oi] = vh;
                        ((__nv_bfloat16*)C1)[oi] = vl;
                    } else if (mode == 3) {               // batched plain fp32
                        ((float*)C0)[(long)z * sC + (long)gr * p1 + gc] = val;
                    } else {                              // mode 4: vT split bf16
                        int b = gr / p1;
                        int rr = gr - b * p1;
                        int h = gc >> 6, d = gc & 63;
                        long oi = ((long)(b * HH + h) * DHH + d) * JJP + NMEM + rr;
                        __nv_bfloat16 vh, vl; split_bf16(val, vh, vl);
                        ((__nv_bfloat16*)C0)[oi] = vh;
                        ((__nv_bfloat16*)C1)[oi] = vl;
                    }
                }
            }
        }
    }
}

// ---------------- host launch ------------------------------------------------

static constexpr size_t MIX_SMEM  = (size_t)HH * JJ * sizeof(float);   // 132096
// proj/dots: BM=128, BN=64 -> stage = (2*128*20 + 2*64*20)*4 = 30720 B, x2 stages
static constexpr int    BIG_SMEM  = 2 * (2 * 128 * 20 + 2 * 64 * 20) * 4;   // 61440
// avk: BM=64, BN=64 -> stage = (2*64*20 + 2*64*20)*4 = 20480 B, x2 stages
static constexpr int    SML_SMEM  = 2 * (2 * 64 * 20 + 2 * 64 * 20) * 4;    // 40960

extern "C" void kernel_launch(void* const* d_in, const int* in_sizes, int n_in,
                              void* d_out, int out_size)
{
    (void)in_sizes; (void)n_in; (void)out_size;
    const float* x   = (const float*)d_in[0];
    const float* ctx = (const float*)d_in[1];
    const float* wq[2]     = {(const float*)d_in[2],  (const float*)d_in[5]};
    const float* wk[2]     = {(const float*)d_in[3],  (const float*)d_in[6]};
    const float* wv[2]     = {(const float*)d_in[4],  (const float*)d_in[7]};
    const float* thpre[2]  = {(const float*)d_in[8],  (const float*)d_in[10]};
    const float* thpost[2] = {(const float*)d_in[9],  (const float*)d_in[11]};
    const float* scp[2]    = {(const float*)d_in[12], (const float*)d_in[13]};
    const float* mk[2]     = {(const float*)d_in[14], (const float*)d_in[16]};
    const float* mv[2]     = {(const float*)d_in[15], (const float*)d_in[17]};
    const float* hs[2]     = {(const float*)d_in[18], (const float*)d_in[19]};
    const float* wo[2]     = {(const float*)d_in[20], (const float*)d_in[21]};
    float* out = (float*)d_out;

    float *qn, *kn, *dots, *scl;
    __nv_bfloat16 *xH,*xL,*cH,*cL,*wTH,*wTL,*qnH,*qnL,*knH,*knL,*vTH,*vTL,*atH,*atL,*ctH,*ctL;
    cudaGetSymbolAddress((void**)&qn,   g_qn);
    cudaGetSymbolAddress((void**)&kn,   g_kn);
    cudaGetSymbolAddress((void**)&dots, g_dots);
    cudaGetSymbolAddress((void**)&scl,  g_scale);
    cudaGetSymbolAddress((void**)&xH,  g_xH);  cudaGetSymbolAddress((void**)&xL,  g_xL);
    cudaGetSymbolAddress((void**)&cH,  g_cH);  cudaGetSymbolAddress((void**)&cL,  g_cL);
    cudaGetSymbolAddress((void**)&wTH, g_wTH); cudaGetSymbolAddress((void**)&wTL, g_wTL);
    cudaGetSymbolAddress((void**)&qnH, g_qnH); cudaGetSymbolAddress((void**)&qnL, g_qnL);
    cudaGetSymbolAddress((void**)&knH, g_knH); cudaGetSymbolAddress((void**)&knL, g_knL);
    cudaGetSymbolAddress((void**)&vTH, g_vTH); cudaGetSymbolAddress((void**)&vTL, g_vTL);
    cudaGetSymbolAddress((void**)&atH, g_atH); cudaGetSymbolAddress((void**)&atL, g_atL);
    cudaGetSymbolAddress((void**)&ctH, g_ctH); cudaGetSymbolAddress((void**)&ctL, g_ctL);

    auto projk = psgemm_kernel<128, 64, 64, 16, false>;   // 8 warps, smaller regs
    auto dotsk = psgemm_kernel<128, 64, 64, 16, true>;
    auto avk   = psgemm_kernel<64, 64, 32, 16, false>;    // 8 warps (was 4)
    cudaFuncSetAttribute(projk, cudaFuncAttributeMaxDynamicSharedMemorySize, BIG_SMEM);
    cudaFuncSetAttribute(dotsk, cudaFuncAttributeMaxDynamicSharedMemorySize, BIG_SMEM);
    cudaFuncSetAttribute(avk,   cudaFuncAttributeMaxDynamicSharedMemorySize, SML_SMEM);
    cudaFuncSetAttribute(mix_softmax_kernel,
                         cudaFuncAttributeMaxDynamicSharedMemorySize, (int)MIX_SMEM);

    // split x once (shared by both layers)
    split_kernel<<<(Bc * Nq * DIM / 4 + 255) / 256, 256>>>(xH, xL, x, (long)Bc * Nq * DIM / 4);

    for (int l = 0; l < 2; l++) {
        scale_kernel<<<1, 16>>>(scl, scp[l]);

        // split context for this layer
        split_kernel<<<(Bc * NCTX * DIM / 4 + 255) / 256, 256>>>(
            cH, cL, ctx + (size_t)l * Bc * NCTX * DIM, (long)Bc * NCTX * DIM / 4);

        // Q = x @ wq -> qn fp32 [b,h,n,d]
        tconv_kernel<<<dim3(HDH / 32, DIM / 32), dim3(32, 8)>>>(wTH, wTL, wq[l], DIM, HDH);
        projk<<<dim3(16, 16, 1), 256, BIG_SMEM>>>(
            Bc * Nq, HDH, DIM, xH, xL, DIM, 0, wTH, wTL, DIM, 0,
            qn, nullptr, 0, nullptr, 0.0f, 1, Nq, Nq, 0);

        // K = ctx @ wk -> kn fp32 rows [NMEM..JJ)
        tconv_kernel<<<dim3(HDH / 32, DIM / 32), dim3(32, 8)>>>(wTH, wTL, wk[l], DIM, HDH);
        projk<<<dim3(16, 32, 1), 256, BIG_SMEM>>>(
            Bc * NCTX, HDH, DIM, cH, cL, DIM, 0, wTH, wTL, DIM, 0,
            kn, nullptr, 0, nullptr, 0.0f, 1, NCTX, JJ, NMEM);

        // V = ctx @ wv -> vT split bf16 [(b,h),d][JJP], rows [NMEM..JJ)
        tconv_kernel<<<dim3(HDH / 32, DIM / 32), dim3(32, 8)>>>(wTH, wTL, wv[l], DIM, HDH);
        projk<<<dim3(16, 32, 1), 256, BIG_SMEM>>>(
            Bc * NCTX, HDH, DIM, cH, cL, DIM, 0, wTH, wTL, DIM, 0,
            vTH, vTL, 0, nullptr, 0.0f, 4, NCTX, 0, 0);

        memfill_kernel<<<64, 256>>>(kn, vTH, vTL, mk[l], mv[l]);

        l2norm_split_kernel<<<(Bc * HH * Nq + 7) / 8, 256>>>(qn, qnH, qnL, Bc * HH * Nq);
        l2norm_split_kernel<<<(Bc * HH * JJ + 7) / 8, 256>>>(kn, knH, knL, Bc * HH * JJ);

        // dots = scale[h] * qn @ kn^T  (z = b*16+h), fp32 out; 33 x-tiles of 64
        dotsk<<<dim3(33, 8, 32), 256, BIG_SMEM>>>(
            Nq, JJ, DHH, qnH, qnL, DHH, (long)Nq * DHH,
            knH, knL, DHH, (long)JJ * DHH,
            dots, nullptr, (long)Nq * JJ, scl, 0.0f, 3, JJ, 0, 0);

        // talking-heads mix + softmax -> attn split bf16 (pitch JJP)
        mix_softmax_kernel<<<Bc * Nq, 256, MIX_SMEM>>>(dots, atH, atL, thpre[l], thpost[l]);

        // out_heads = hs[h] * attn @ v -> cat split bf16 [b,n,(h,d)]
        avk<<<dim3(1, 16, 32), 256, SML_SMEM>>>(
            Nq, DHH, JJP, atH, atL, JJP, (long)Nq * JJP,
            vTH, vTL, JJP, (long)DHH * JJP,
            ctH, ctL, 0, hs[l], 0.0f, 2, Nq, 0, 0);

        // out (+)= cat @ wo
        tconv_kernel<<<dim3(DIM / 32, HDH / 32), dim3(32, 8)>>>(wTH, wTL, wo[l], HDH, DIM);
        projk<<<dim3(16, 16, 1), 256, BIG_SMEM>>>(
            Bc * Nq, DIM, HDH, ctH, ctL, HDH, 0, wTH, wTL, HDH, 0,
            out, nullptr, 0, nullptr, (l == 0 ? 0.0f : 1.0f), 0, DIM, 0, 0);
    }
}

// round 14
// speedup vs baseline: 1.0764x; 1.0764x over previous
#include <cuda_runtime.h>
#include <cuda_bf16.h>
#include <math.h>
#include <stdint.h>

// Problem constants
#define HH 16
#define DHH 64
static constexpr int Bc   = 2;
static constexpr int Nq   = 1024;
static constexpr int NCTX = 2048;
static constexpr int DIM  = 1024;
static constexpr int NMEM = 16;
static constexpr int JJ   = NCTX + NMEM;   // 2064
static constexpr int JJP  = 2080;          // padded to multiple of 32 (BK)
static constexpr int HDH  = HH * DHH;      // 1024

// ---------------- scratch (device globals) ----------------------------------
__device__ float g_qn[(size_t)Bc * HH * Nq * DHH];
__device__ float g_kn[(size_t)Bc * HH * JJ * DHH];
__device__ float g_dots[(size_t)Bc * HH * Nq * (size_t)JJ];
__device__ float g_scale[HH];

// pre-split bf16 operand arrays (hi / lo)
__device__ __align__(16) __nv_bfloat16 g_xH [(size_t)Bc * Nq * DIM];
__device__ __align__(16) __nv_bfloat16 g_xL [(size_t)Bc * Nq * DIM];
__device__ __align__(16) __nv_bfloat16 g_cH [(size_t)Bc * NCTX * DIM];
__device__ __align__(16) __nv_bfloat16 g_cL [(size_t)Bc * NCTX * DIM];
__device__ __align__(16) __nv_bfloat16 g_wTH[(size_t)HDH * DIM];
__device__ __align__(16) __nv_bfloat16 g_wTL[(size_t)HDH * DIM];
__device__ __align__(16) __nv_bfloat16 g_qnH[(size_t)Bc * HH * Nq * DHH];
__device__ __align__(16) __nv_bfloat16 g_qnL[(size_t)Bc * HH * Nq * DHH];
__device__ __align__(16) __nv_bfloat16 g_knH[(size_t)Bc * HH * JJ * DHH];
__device__ __align__(16) __nv_bfloat16 g_knL[(size_t)Bc * HH * JJ * DHH];
__device__ __align__(16) __nv_bfloat16 g_vTH[(size_t)Bc * HH * DHH * JJP];
__device__ __align__(16) __nv_bfloat16 g_vTL[(size_t)Bc * HH * DHH * JJP];
__device__ __align__(16) __nv_bfloat16 g_atH[(size_t)Bc * HH * Nq * JJP];
__device__ __align__(16) __nv_bfloat16 g_atL[(size_t)Bc * HH * Nq * JJP];
__device__ __align__(16) __nv_bfloat16 g_ctH[(size_t)Bc * Nq * HDH];
__device__ __align__(16) __nv_bfloat16 g_ctL[(size_t)Bc * Nq * HDH];

// ---------------- split helpers ---------------------------------------------
__device__ __forceinline__ uint32_t pack_bf2(__nv_bfloat16 a, __nv_bfloat16 b) {
    return ((uint32_t)__bfloat16_as_ushort(b) << 16) | (uint32_t)__bfloat16_as_ushort(a);
}
__device__ __forceinline__ void split_bf16(float x, __nv_bfloat16& h, __nv_bfloat16& l) {
    h = __float2bfloat16(x);
    l = __float2bfloat16(x - __bfloat162float(h));
}

// ---------------- tiny kernels ----------------------------------------------

__global__ void scale_kernel(float* __restrict__ out, const float* __restrict__ p) {
    int h = threadIdx.x;
    if (h < HH) out[h] = 1.0f / fmaxf(expf(p[h]), 0.01f);
}

__global__ void split_kernel(__nv_bfloat16* __restrict__ H, __nv_bfloat16* __restrict__ L,
                             const float* __restrict__ src, long n4) {
    long i = blockIdx.x * (long)blockDim.x + threadIdx.x;
    if (i >= n4) return;
    float4 v = reinterpret_cast<const float4*>(src)[i];
    __nv_bfloat16 h0,l0,h1,l1,h2,l2,h3,l3;
    split_bf16(v.x,h0,l0); split_bf16(v.y,h1,l1);
    split_bf16(v.z,h2,l2); split_bf16(v.w,h3,l3);
    uint2 hw = make_uint2(pack_bf2(h0,h1), pack_bf2(h2,h3));
    uint2 lw = make_uint2(pack_bf2(l0,l1), pack_bf2(l2,l3));
    reinterpret_cast<uint2*>(H)[i] = hw;
    reinterpret_cast<uint2*>(L)[i] = lw;
}

__global__ void tconv_kernel(__nv_bfloat16* __restrict__ H, __nv_bfloat16* __restrict__ L,
                             const float* __restrict__ src, int K, int N) {
    __shared__ float t[32][33];
    int n0 = blockIdx.x * 32, k0 = blockIdx.y * 32;
    for (int yy = threadIdx.y; yy < 32; yy += 8)
        t[yy][threadIdx.x] = src[(long)(k0 + yy) * N + n0 + threadIdx.x];
    __syncthreads();
    for (int yy = threadIdx.y; yy < 32; yy += 8) {
        float v = t[threadIdx.x][yy];
        long o = (long)(n0 + yy) * K + k0 + threadIdx.x;
        __nv_bfloat16 h, l; split_bf16(v, h, l);
        H[o] = h; L[o] = l;
    }
}

__global__ void memfill_kernel(float* __restrict__ kn,
                               __nv_bfloat16* __restrict__ vTH, __nv_bfloat16* __restrict__ vTL,
                               const float* __restrict__ mk, const float* __restrict__ mv) {
    int idx = blockIdx.x * blockDim.x + threadIdx.x;
    const int total = HH * NMEM * DHH;
    if (idx >= total) return;
    int h   = idx / (NMEM * DHH);
    int rem = idx % (NMEM * DHH);
    int m = rem / DHH, d = rem % DHH;
    float k = mk[idx], v = mv[idx];
    __nv_bfloat16 vh, vl; split_bf16(v, vh, vl);
    for (int b = 0; b < Bc; b++) {
        kn[(((size_t)(b * HH + h) * JJ) + m) * DHH + d] = k;
        size_t base = ((size_t)(b * HH + h) * DHH + d) * JJP;
        vTH[base + m] = vh;            vTL[base + m] = vl;
        vTH[base + JJ + m] = __float2bfloat16(0.f);
        vTL[base + JJ + m] = __float2bfloat16(0.f);
    }
}

__global__ void l2norm_split_kernel(const float* __restrict__ src,
                                    __nv_bfloat16* __restrict__ H,
                                    __nv_bfloat16* __restrict__ L, int rows) {
    int row = blockIdx.x * 8 + (threadIdx.x >> 5);
    if (row >= rows) return;
    int lane = threadIdx.x & 31;
    float2 v = reinterpret_cast<const float2*>(src + (size_t)row * DHH)[lane];
    float ss = v.x * v.x + v.y * v.y;
    #pragma unroll
    for (int o = 16; o; o >>= 1) ss += __shfl_xor_sync(0xffffffffu, ss, o);
    float inv = 1.0f / fmaxf(sqrtf(ss), 1e-12f);
    __nv_bfloat16 hx,lx,hy,ly;
    split_bf16(v.x * inv, hx, lx);
    split_bf16(v.y * inv, hy, ly);
    reinterpret_cast<uint32_t*>(H)[(size_t)row * 32 + lane] = pack_bf2(hx, hy);
    reinterpret_cast<uint32_t*>(L)[(size_t)row * 32 + lane] = pack_bf2(lx, ly);
}

// ---------------- fused talking-heads pre-mix + softmax + post-mix ----------
__global__ void mix_softmax_kernel(const float* __restrict__ dots,
                                   __nv_bfloat16* __restrict__ atH,
                                   __nv_bfloat16* __restrict__ atL,
                                   const float* __restrict__ th_pre,
                                   const float* __restrict__ th_post) {
    extern __shared__ float sh[];
    __shared__ float s_pre[HH * HH], s_post[HH * HH];
    __shared__ float red[HH][8];
    __shared__ float gmax[HH], gsum[HH], Mmat[HH * HH];

    const int bi = blockIdx.x;
    const int b = bi / Nq, i = bi % Nq;
    const int tid = threadIdx.x;
    const int warp = tid >> 5, lane = tid & 31;

    s_pre[tid]  = th_pre[tid];
    s_post[tid] = th_post[tid];

    for (int h = 0; h < HH; h++) {
        const float* src = dots + (((size_t)(b * HH + h) * Nq + i) * JJ);
        for (int j = tid; j < JJ; j += 256) sh[h * JJ + j] = src[j];
    }
    __syncthreads();

    float lmax[HH];
    #pragma unroll
    for (int g = 0; g < HH; g++) lmax[g] = -1e30f;
    for (int j = tid; j < JJ; j += 256) {
        float d[HH];
        #pragma unroll
        for (int h = 0; h < HH; h++) d[h] = sh[h * JJ + j];
        #pragma unroll
        for (int g = 0; g < HH; g++) {
            float m = 0.0f;
            #pragma unroll
            for (int h = 0; h < HH; h++) m = fmaf(s_pre[g * HH + h], d[h], m);
            sh[g * JJ + j] = m;
            lmax[g] = fmaxf(lmax[g], m);
        }
    }
    __syncthreads();
    #pragma unroll
    for (int g = 0; g < HH; g++) {
        float v = lmax[g];
        #pragma unroll
        for (int o = 16; o; o >>= 1) v = fmaxf(v, __shfl_xor_sync(0xffffffffu, v, o));
        if (lane == 0) red[g][warp] = v;
    }
    __syncthreads();
    if (tid < HH) {
        float v = red[tid][0];
        #pragma unroll
        for (int w = 1; w < 8; w++) v = fmaxf(v, red[tid][w]);
        gmax[tid] = v;
    }
    __syncthreads();

    float lsum[HH];
    #pragma unroll
    for (int g = 0; g < HH; g++) lsum[g] = 0.0f;
    for (int j = tid; j < JJ; j += 256) {
        #pragma unroll
        for (int g = 0; g < HH; g++) {
            float e = __expf(sh[g * JJ + j] - gmax[g]);
            sh[g * JJ + j] = e;
            lsum[g] += e;
        }
    }
    __syncthreads();
    #pragma unroll
    for (int g = 0; g < HH; g++) {
        float v = lsum[g];
        #pragma unroll
        for (int o = 16; o; o >>= 1) v += __shfl_xor_sync(0xffffffffu, v, o);
        if (lane == 0) red[g][warp] = v;
    }
    __syncthreads();
    if (tid < HH) {
        float v = 0.0f;
        #pragma unroll
        for (int w = 0; w < 8; w++) v += red[tid][w];
        gsum[tid] = v;
    }
    __syncthreads();
    Mmat[tid] = s_post[tid] / gsum[tid & 15];
    __syncthreads();

    for (int j = tid; j < JJP; j += 256) {
        float e[HH];
        bool in = (j < JJ);
        #pragma unroll
        for (int h = 0; h < HH; h++) e[h] = in ? sh[h * JJ + j] : 0.0f;
        #pragma unroll
        for (int g = 0; g < HH; g++) {
            float o = 0.0f;
            #pragma unroll
            for (int h = 0; h < HH; h++) o = fmaf(Mmat[g * HH + h], e[h], o);
            size_t oi = (((size_t)(b * HH + g) * Nq + i) * JJP) + j;
            __nv_bfloat16 oh, ol; split_bf16(o, oh, ol);
            atH[oi] = oh; atL[oi] = ol;
        }
    }
}

// ---------------- pre-split bf16x2 GEMM: cp.async pipeline + ldmatrix -------
// A: [M][K] bf16 hi/lo row-major.  B: [Nc][K] bf16 hi/lo row-major (n-major).
// C = A @ B^T, fp32 accum via 3-term mma (loH + hiL + hiH). K % 32 == 0.

__device__ __forceinline__ void cp16(uint32_t dst, const void* src) {
    asm volatile("cp.async.ca.shared.global [%0], [%1], 16;" :: "r"(dst), "l"(src));
}
__device__ __forceinline__ void cpcommit() { asm volatile("cp.async.commit_group;"); }
template<int N> __device__ __forceinline__ void cpwait() {
    asm volatile("cp.async.wait_group %0;" :: "n"(N));
}

__device__ __forceinline__ void ldsm_x4(uint32_t& r0, uint32_t& r1, uint32_t& r2, uint32_t& r3,
                                        uint32_t addr) {
    asm volatile("ldmatrix.sync.aligned.m8n8.x4.shared.b16 {%0,%1,%2,%3}, [%4];"
                 : "=r"(r0), "=r"(r1), "=r"(r2), "=r"(r3) : "r"(addr));
}

__device__ __forceinline__ void mma_bf16(float* c, const uint32_t* a, const uint32_t* b) {
    asm volatile(
        "mma.sync.aligned.m16n8k16.row.col.f32.bf16.bf16.f32 "
        "{%0,%1,%2,%3}, {%4,%5,%6,%7}, {%8,%9}, {%0,%1,%2,%3};"
        : "+f"(c[0]), "+f"(c[1]), "+f"(c[2]), "+f"(c[3])
        : "r"(a[0]), "r"(a[1]), "r"(a[2]), "r"(a[3]),
          "r"(b[0]), "r"(b[1]));
}

template<int BM, int BN, int WM, int WN, bool GUARDN>
__global__ void __launch_bounds__((BM / WM) * (BN / WN) * 32)
psgemm_kernel(
    int M, int Nc, int K,
    const __nv_bfloat16* __restrict__ AH, const __nv_bfloat16* __restrict__ AL,
    long lda, long sA,
    const __nv_bfloat16* __restrict__ BH, const __nv_bfloat16* __restrict__ BL,
    long ldb, long sB,
    void* C0, void* C1, long sC,
    const float* __restrict__ alphaVec,
    float beta, int mode, int p1, int p2, int p3)
{
    constexpr int BK  = 32;
    constexpr int NTH = (BM / WM) * (BN / WN) * 32;
    constexpr int PA  = BK / 2 + 4;          // 20 u32 words pitch (A and B)
    constexpr int AW  = BM * PA;
    constexpr int BW  = BN * PA;
    constexpr int SW  = 2 * AW + 2 * BW;
    constexpr int MFR = WM / 16;
    constexpr int NFR = WN / 8;              // even (16-col B ldmatrix pairs)

    extern __shared__ uint32_t smem[];
    const uint32_t smem_addr = (uint32_t)__cvta_generic_to_shared(smem);

    const int z = blockIdx.z;
    const __nv_bfloat16* Ah = AH + (long)z * sA;
    const __nv_bfloat16* Al = AL + (long)z * sA;
    const __nv_bfloat16* Bh = BH + (long)z * sB;
    const __nv_bfloat16* Bl = BL + (long)z * sB;

    const int tid  = threadIdx.x;
    const int warp = tid >> 5;
    const int lane = tid & 31;
    const int g    = lane >> 2;
    const int tg   = lane & 3;
    const int wr   = warp / (BN / WN);
    const int wc   = warp % (BN / WN);
    const int rowBase = blockIdx.y * BM;
    const int colBase = blockIdx.x * BN;

    // ldmatrix lane geometry
    const int a_row  = (lane & 15);          // row within m16 frag
    const int a_seg  = (lane >> 4) * 4;      // +4 words for k8..15 mats
    const int b_row  = (lane & 7) + ((lane >> 4) << 3);  // row within n16 pair
    const int b_seg  = ((lane >> 3) & 1) * 4;            // +4 words for k8..15

    float acc[MFR][NFR][4];
    #pragma unroll
    for (int i = 0; i < MFR; i++)
        #pragma unroll
        for (int j = 0; j < NFR; j++)
            #pragma unroll
            for (int q = 0; q < 4; q++) acc[i][j][q] = 0.0f;

    auto load_tile = [&](int stage, int k0) {
        uint32_t base = smem_addr + (uint32_t)stage * SW * 4;
        #pragma unroll 2
        for (int idx = tid; idx < BM * 4; idx += NTH) {
            int r  = idx >> 2;
            int c8 = idx & 3;
            long go = (long)(rowBase + r) * lda + k0 + c8 * 8;
            uint32_t d = base + (uint32_t)(r * PA + c8 * 4) * 4;
            cp16(d, Ah + go);
            cp16(d + AW * 4, Al + go);
        }
        #pragma unroll 2
        for (int idx = tid; idx < BN * 4; idx += NTH) {
            int c  = idx >> 2;
            int k8 = idx & 3;
            int gc = colBase + c;
            uint32_t d = base + (uint32_t)(2 * AW + c * PA + k8 * 4) * 4;
            if (!GUARDN || gc < Nc) {
                long go = (long)gc * ldb + k0 + k8 * 8;
                cp16(d, Bh + go);
                cp16(d + BW * 4, Bl + go);
            } else {
                uint4 zz = make_uint4(0, 0, 0, 0);
                *reinterpret_cast<uint4*>(&smem[stage * SW + 2 * AW + c * PA + k8 * 4]) = zz;
                *reinterpret_cast<uint4*>(&smem[stage * SW + 2 * AW + BW + c * PA + k8 * 4]) = zz;
            }
        }
    };

    const int nK = K / BK;
    load_tile(0, 0);
    cpcommit();

    for (int kt = 0; kt < nK; kt++) {
        int cur = kt & 1;
        if (kt + 1 < nK) load_tile((kt + 1) & 1, (kt + 1) * BK);
        cpcommit();
        cpwait<1>();
        __syncthreads();

        uint32_t baseB = smem_addr + (uint32_t)cur * SW * 4;
        uint32_t aH = baseB;
        uint32_t aL = baseB + AW * 4;
        uint32_t bH = baseB + 2 * AW * 4;
        uint32_t bL = bH + BW * 4;

        #pragma unroll
        for (int kk = 0; kk < BK; kk += 16) {
            const int kp = kk / 2;
            uint32_t afH[MFR][4], afL[MFR][4];
            uint32_t bfH[NFR][2], bfL[NFR][2];
            #pragma unroll
            for (int mi = 0; mi < MFR; mi++) {
                uint32_t off = (uint32_t)((wr * WM + mi * 16 + a_row) * PA + kp + a_seg) * 4;
                ldsm_x4(afH[mi][0], afH[mi][1], afH[mi][2], afH[mi][3], aH + off);
                ldsm_x4(afL[mi][0], afL[mi][1], afL[mi][2], afL[mi][3], aL + off);
            }
            #pragma unroll
            for (int np = 0; np < NFR / 2; np++) {
                uint32_t off = (uint32_t)((wc * WN + np * 16 + b_row) * PA + kp + b_seg) * 4;
                ldsm_x4(bfH[2*np][0], bfH[2*np][1], bfH[2*np+1][0], bfH[2*np+1][1], bH + off);
                ldsm_x4(bfL[2*np][0], bfL[2*np][1], bfL[2*np+1][0], bfL[2*np+1][1], bL + off);
            }
            #pragma unroll
            for (int mi = 0; mi < MFR; mi++)
                #pragma unroll
                for (int ni = 0; ni < NFR; ni++) {
                    float* c = acc[mi][ni];
                    mma_bf16(c, afL[mi], bfH[ni]);
                    mma_bf16(c, afH[mi], bfL[ni]);
                    mma_bf16(c, afH[mi], bfH[ni]);
                }
        }
        __syncthreads();
    }

    float alpha = 1.0f;
    if (alphaVec) alpha = alphaVec[z % HH];

    #pragma unroll
    for (int mi = 0; mi < MFR; mi++) {
        #pragma unroll
        for (int half = 0; half < 2; half++) {
            int gr = rowBase + wr * WM + mi * 16 + g + half * 8;
            if (gr >= M) continue;
            #pragma unroll
            for (int ni = 0; ni < NFR; ni++) {
                #pragma unroll
                for (int e = 0; e < 2; e++) {
                    int gc = colBase + wc * WN + ni * 8 + tg * 2 + e;
                    if (gc >= Nc) continue;
                    float val = alpha * acc[mi][ni][half * 2 + e];
                    if (mode == 0) {
                        float* cp = (float*)C0 + (long)gr * p1 + gc;
                        *cp = (beta == 0.0f) ? val : fmaf(beta, *cp, val);
                    } else if (mode == 1) {
                        int b = gr / p1;
                        int rr = gr - b * p1;
                        int h = gc >> 6, d = gc & 63;
                        ((float*)C0)[(((long)(b * HH + h) * p2 + p3 + rr) << 6) + d] = val;
                    } else if (mode == 2) {
                        int b = z >> 4, h = z & 15;
                        long oi = (((long)(b * p1 + gr) * HH + h) << 6) + gc;
                        __nv_bfloat16 vh, vl; split_bf16(val, vh, vl);
                        ((__nv_bfloat16*)C0)[oi] = vh;
                        ((__nv_bfloat16*)C1)[oi] = vl;
                    } else if (mode == 3) {
                        ((float*)C0)[(long)z * sC + (long)gr * p1 + gc] = val;
                    } else {
                        int b = gr / p1;
                        int rr = gr - b * p1;
                        int h = gc >> 6, d = gc & 63;
                        long oi = ((long)(b * HH + h) * DHH + d) * JJP + NMEM + rr;
                        __nv_bfloat16 vh, vl; split_bf16(val, vh, vl);
                        ((__nv_bfloat16*)C0)[oi] = vh;
                        ((__nv_bfloat16*)C1)[oi] = vl;
                    }
                }
            }
        }
    }
}

// ---------------- host launch ------------------------------------------------

static constexpr size_t MIX_SMEM  = (size_t)HH * JJ * sizeof(float);        // 132096
static constexpr int    BIG_SMEM  = 2 * (2 * 128 * 20 + 2 * 128 * 20) * 4;  // 81920
static constexpr int    SML_SMEM  = 2 * (2 * 64 * 20 + 2 * 64 * 20) * 4;    // 40960

extern "C" void kernel_launch(void* const* d_in, const int* in_sizes, int n_in,
                              void* d_out, int out_size)
{
    (void)in_sizes; (void)n_in; (void)out_size;
    const float* x   = (const float*)d_in[0];
    const float* ctx = (const float*)d_in[1];
    const float* wq[2]     = {(const float*)d_in[2],  (const float*)d_in[5]};
    const float* wk[2]     = {(const float*)d_in[3],  (const float*)d_in[6]};
    const float* wv[2]     = {(const float*)d_in[4],  (const float*)d_in[7]};
    const float* thpre[2]  = {(const float*)d_in[8],  (const float*)d_in[10]};
    const float* thpost[2] = {(const float*)d_in[9],  (const float*)d_in[11]};
    const float* scp[2]    = {(const float*)d_in[12], (const float*)d_in[13]};
    const float* mk[2]     = {(const float*)d_in[14], (const float*)d_in[16]};
    const float* mv[2]     = {(const float*)d_in[15], (const float*)d_in[17]};
    const float* hs[2]     = {(const float*)d_in[18], (const float*)d_in[19]};
    const float* wo[2]     = {(const float*)d_in[20], (const float*)d_in[21]};
    float* out = (float*)d_out;

    float *qn, *kn, *dots, *scl;
    __nv_bfloat16 *xH,*xL,*cH,*cL,*wTH,*wTL,*qnH,*qnL,*knH,*knL,*vTH,*vTL,*atH,*atL,*ctH,*ctL;
    cudaGetSymbolAddress((void**)&qn,   g_qn);
    cudaGetSymbolAddress((void**)&kn,   g_kn);
    cudaGetSymbolAddress((void**)&dots, g_dots);
    cudaGetSymbolAddress((void**)&scl,  g_scale);
    cudaGetSymbolAddress((void**)&xH,  g_xH);  cudaGetSymbolAddress((void**)&xL,  g_xL);
    cudaGetSymbolAddress((void**)&cH,  g_cH);  cudaGetSymbolAddress((void**)&cL,  g_cL);
    cudaGetSymbolAddress((void**)&wTH, g_wTH); cudaGetSymbolAddress((void**)&wTL, g_wTL);
    cudaGetSymbolAddress((void**)&qnH, g_qnH); cudaGetSymbolAddress((void**)&qnL, g_qnL);
    cudaGetSymbolAddress((void**)&knH, g_knH); cudaGetSymbolAddress((void**)&knL, g_knL);
    cudaGetSymbolAddress((void**)&vTH, g_vTH); cudaGetSymbolAddress((void**)&vTL, g_vTL);
    cudaGetSymbolAddress((void**)&atH, g_atH); cudaGetSymbolAddress((void**)&atL, g_atL);
    cudaGetSymbolAddress((void**)&ctH, g_ctH); cudaGetSymbolAddress((void**)&ctL, g_ctL);

    auto projk = psgemm_kernel<128, 128, 64, 32, false>;
    auto dotsk = psgemm_kernel<128, 128, 64, 32, true>;
    auto avk   = psgemm_kernel<64, 64, 32, 32, false>;
    cudaFuncSetAttribute(projk, cudaFuncAttributeMaxDynamicSharedMemorySize, BIG_SMEM);
    cudaFuncSetAttribute(dotsk, cudaFuncAttributeMaxDynamicSharedMemorySize, BIG_SMEM);
    cudaFuncSetAttribute(avk,   cudaFuncAttributeMaxDynamicSharedMemorySize, SML_SMEM);
    cudaFuncSetAttribute(mix_softmax_kernel,
                         cudaFuncAttributeMaxDynamicSharedMemorySize, (int)MIX_SMEM);

    // split x once (shared by both layers)
    split_kernel<<<(Bc * Nq * DIM / 4 + 255) / 256, 256>>>(xH, xL, x, (long)Bc * Nq * DIM / 4);

    for (int l = 0; l < 2; l++) {
        scale_kernel<<<1, 16>>>(scl, scp[l]);

        split_kernel<<<(Bc * NCTX * DIM / 4 + 255) / 256, 256>>>(
            cH, cL, ctx + (size_t)l * Bc * NCTX * DIM, (long)Bc * NCTX * DIM / 4);

        // Q = x @ wq -> qn fp32 [b,h,n,d]
        tconv_kernel<<<dim3(HDH / 32, DIM / 32), dim3(32, 8)>>>(wTH, wTL, wq[l], DIM, HDH);
        projk<<<dim3(8, 16, 1), 256, BIG_SMEM>>>(
            Bc * Nq, HDH, DIM, xH, xL, DIM, 0, wTH, wTL, DIM, 0,
            qn, nullptr, 0, nullptr, 0.0f, 1, Nq, Nq, 0);

        // K = ctx @ wk -> kn fp32 rows [NMEM..JJ)
        tconv_kernel<<<dim3(HDH / 32, DIM / 32), dim3(32, 8)>>>(wTH, wTL, wk[l], DIM, HDH);
        projk<<<dim3(8, 32, 1), 256, BIG_SMEM>>>(
            Bc * NCTX, HDH, DIM, cH, cL, DIM, 0, wTH, wTL, DIM, 0,
            kn, nullptr, 0, nullptr, 0.0f, 1, NCTX, JJ, NMEM);

        // V = ctx @ wv -> vT split bf16, rows [NMEM..JJ)
        tconv_kernel<<<dim3(HDH / 32, DIM / 32), dim3(32, 8)>>>(wTH, wTL, wv[l], DIM, HDH);
        projk<<<dim3(8, 32, 1), 256, BIG_SMEM>>>(
            Bc * NCTX, HDH, DIM, cH, cL, DIM, 0, wTH, wTL, DIM, 0,
            vTH, vTL, 0, nullptr, 0.0f, 4, NCTX, 0, 0);

        memfill_kernel<<<64, 256>>>(kn, vTH, vTL, mk[l], mv[l]);

        l2norm_split_kernel<<<(Bc * HH * Nq + 7) / 8, 256>>>(qn, qnH, qnL, Bc * HH * Nq);
        l2norm_split_kernel<<<(Bc * HH * JJ + 7) / 8, 256>>>(kn, knH, knL, Bc * HH * JJ);

        // dots = scale[h] * qn @ kn^T  (z = b*16+h), fp32 out
        dotsk<<<dim3(17, 8, 32), 256, BIG_SMEM>>>(
            Nq, JJ, DHH, qnH, qnL, DHH, (long)Nq * DHH,
            knH, knL, DHH, (long)JJ * DHH,
            dots, nullptr, (long)Nq * JJ, scl, 0.0f, 3, JJ, 0, 0);

        // talking-heads mix + softmax -> attn split bf16 (pitch JJP)
        mix_softmax_kernel<<<Bc * Nq, 256, MIX_SMEM>>>(dots, atH, atL, thpre[l], thpost[l]);

        // out_heads = hs[h] * attn @ v -> cat split bf16 [b,n,(h,d)]
        avk<<<dim3(1, 16, 32), 128, SML_SMEM>>>(
            Nq, DHH, JJP, atH, atL, JJP, (long)Nq * JJP,
            vTH, vTL, JJP, (long)DHH * JJP,
            ctH, ctL, 0, hs[l], 0.0f, 2, Nq, 0, 0);

        // out (+)= cat @ wo
        tconv_kernel<<<dim3(DIM / 32, HDH / 32), dim3(32, 8)>>>(wTH, wTL, wo[l], HDH, DIM);
        projk<<<dim3(8, 16, 1), 256, BIG_SMEM>>>(
            Bc * Nq, DIM, HDH, ctH, ctL, HDH, 0, wTH, wTL, HDH, 0,
            out, nullptr, 0, nullptr, (l == 0 ? 0.0f : 1.0f), 0, DIM, 0, 0);
    }
}

// round 15
// speedup vs baseline: 1.1165x; 1.0372x over previous
#include <cuda_runtime.h>
#include <cuda_bf16.h>
#include <math.h>
#include <stdint.h>

// Problem constants
#define HH 16
#define DHH 64
static constexpr int Bc   = 2;
static constexpr int Nq   = 1024;
static constexpr int NCTX = 2048;
static constexpr int DIM  = 1024;
static constexpr int NMEM = 16;
static constexpr int JJ   = NCTX + NMEM;   // 2064
static constexpr int JJP  = 2080;          // padded to multiple of 32 (BK)
static constexpr int HDH  = HH * DHH;      // 1024

// ---------------- scratch (device globals) ----------------------------------
__device__ float g_qn[(size_t)Bc * HH * Nq * DHH];
__device__ float g_kn[(size_t)Bc * HH * JJ * DHH];
__device__ float g_dots[(size_t)Bc * HH * Nq * (size_t)JJ];
__device__ float g_scale[HH];

// pre-split bf16 operand arrays (hi / lo)
__device__ __align__(16) __nv_bfloat16 g_xH [(size_t)Bc * Nq * DIM];
__device__ __align__(16) __nv_bfloat16 g_xL [(size_t)Bc * Nq * DIM];
__device__ __align__(16) __nv_bfloat16 g_cH [(size_t)Bc * NCTX * DIM];
__device__ __align__(16) __nv_bfloat16 g_cL [(size_t)Bc * NCTX * DIM];
__device__ __align__(16) __nv_bfloat16 g_wTH[(size_t)HDH * DIM];
__device__ __align__(16) __nv_bfloat16 g_wTL[(size_t)HDH * DIM];
__device__ __align__(16) __nv_bfloat16 g_qnH[(size_t)Bc * HH * Nq * DHH];
__device__ __align__(16) __nv_bfloat16 g_qnL[(size_t)Bc * HH * Nq * DHH];
__device__ __align__(16) __nv_bfloat16 g_knH[(size_t)Bc * HH * JJ * DHH];
__device__ __align__(16) __nv_bfloat16 g_knL[(size_t)Bc * HH * JJ * DHH];
__device__ __align__(16) __nv_bfloat16 g_vTH[(size_t)Bc * HH * DHH * JJP];
__device__ __align__(16) __nv_bfloat16 g_vTL[(size_t)Bc * HH * DHH * JJP];
__device__ __align__(16) __nv_bfloat16 g_atH[(size_t)Bc * HH * Nq * JJP];
__device__ __align__(16) __nv_bfloat16 g_atL[(size_t)Bc * HH * Nq * JJP];
__device__ __align__(16) __nv_bfloat16 g_ctH[(size_t)Bc * Nq * HDH];
__device__ __align__(16) __nv_bfloat16 g_ctL[(size_t)Bc * Nq * HDH];

// ---------------- split helpers ---------------------------------------------
__device__ __forceinline__ uint32_t pack_bf2(__nv_bfloat16 a, __nv_bfloat16 b) {
    return ((uint32_t)__bfloat16_as_ushort(b) << 16) | (uint32_t)__bfloat16_as_ushort(a);
}
__device__ __forceinline__ void split_bf16(float x, __nv_bfloat16& h, __nv_bfloat16& l) {
    h = __float2bfloat16(x);
    l = __float2bfloat16(x - __bfloat162float(h));
}

// ---------------- tiny kernels ----------------------------------------------

__global__ void scale_kernel(float* __restrict__ out, const float* __restrict__ p) {
    int h = threadIdx.x;
    if (h < HH) out[h] = 1.0f / fmaxf(expf(p[h]), 0.01f);
}

__global__ void split_kernel(__nv_bfloat16* __restrict__ H, __nv_bfloat16* __restrict__ L,
                             const float* __restrict__ src, long n4) {
    long i = blockIdx.x * (long)blockDim.x + threadIdx.x;
    if (i >= n4) return;
    float4 v = reinterpret_cast<const float4*>(src)[i];
    __nv_bfloat16 h0,l0,h1,l1,h2,l2,h3,l3;
    split_bf16(v.x,h0,l0); split_bf16(v.y,h1,l1);
    split_bf16(v.z,h2,l2); split_bf16(v.w,h3,l3);
    uint2 hw = make_uint2(pack_bf2(h0,h1), pack_bf2(h2,h3));
    uint2 lw = make_uint2(pack_bf2(l0,l1), pack_bf2(l2,l3));
    reinterpret_cast<uint2*>(H)[i] = hw;
    reinterpret_cast<uint2*>(L)[i] = lw;
}

__global__ void tconv_kernel(__nv_bfloat16* __restrict__ H, __nv_bfloat16* __restrict__ L,
                             const float* __restrict__ src, int K, int N) {
    __shared__ float t[32][33];
    int n0 = blockIdx.x * 32, k0 = blockIdx.y * 32;
    for (int yy = threadIdx.y; yy < 32; yy += 8)
        t[yy][threadIdx.x] = src[(long)(k0 + yy) * N + n0 + threadIdx.x];
    __syncthreads();
    for (int yy = threadIdx.y; yy < 32; yy += 8) {
        float v = t[threadIdx.x][yy];
        long o = (long)(n0 + yy) * K + k0 + threadIdx.x;
        __nv_bfloat16 h, l; split_bf16(v, h, l);
        H[o] = h; L[o] = l;
    }
}

__global__ void memfill_kernel(float* __restrict__ kn,
                               __nv_bfloat16* __restrict__ vTH, __nv_bfloat16* __restrict__ vTL,
                               const float* __restrict__ mk, const float* __restrict__ mv) {
    int idx = blockIdx.x * blockDim.x + threadIdx.x;
    const int total = HH * NMEM * DHH;
    if (idx >= total) return;
    int h   = idx / (NMEM * DHH);
    int rem = idx % (NMEM * DHH);
    int m = rem / DHH, d = rem % DHH;
    float k = mk[idx], v = mv[idx];
    __nv_bfloat16 vh, vl; split_bf16(v, vh, vl);
    for (int b = 0; b < Bc; b++) {
        kn[(((size_t)(b * HH + h) * JJ) + m) * DHH + d] = k;
        size_t base = ((size_t)(b * HH + h) * DHH + d) * JJP;
        vTH[base + m] = vh;            vTL[base + m] = vl;
        vTH[base + JJ + m] = __float2bfloat16(0.f);
        vTL[base + JJ + m] = __float2bfloat16(0.f);
    }
}

__global__ void l2norm_split_kernel(const float* __restrict__ src,
                                    __nv_bfloat16* __restrict__ H,
                                    __nv_bfloat16* __restrict__ L, int rows) {
    int row = blockIdx.x * 8 + (threadIdx.x >> 5);
    if (row >= rows) return;
    int lane = threadIdx.x & 31;
    float2 v = reinterpret_cast<const float2*>(src + (size_t)row * DHH)[lane];
    float ss = v.x * v.x + v.y * v.y;
    #pragma unroll
    for (int o = 16; o; o >>= 1) ss += __shfl_xor_sync(0xffffffffu, ss, o);
    float inv = 1.0f / fmaxf(sqrtf(ss), 1e-12f);
    __nv_bfloat16 hx,lx,hy,ly;
    split_bf16(v.x * inv, hx, lx);
    split_bf16(v.y * inv, hy, ly);
    reinterpret_cast<uint32_t*>(H)[(size_t)row * 32 + lane] = pack_bf2(hx, hy);
    reinterpret_cast<uint32_t*>(L)[(size_t)row * 32 + lane] = pack_bf2(lx, ly);
}

// ---------------- fused talking-heads pre-mix + softmax + post-mix ----------
__global__ void mix_softmax_kernel(const float* __restrict__ dots,
                                   __nv_bfloat16* __restrict__ atH,
                                   __nv_bfloat16* __restrict__ atL,
                                   const float* __restrict__ th_pre,
                                   const float* __restrict__ th_post) {
    extern __shared__ float sh[];
    __shared__ float s_pre[HH * HH], s_post[HH * HH];
    __shared__ float red[HH][8];
    __shared__ float gmax[HH], gsum[HH], Mmat[HH * HH];

    const int bi = blockIdx.x;
    const int b = bi / Nq, i = bi % Nq;
    const int tid = threadIdx.x;
    const int warp = tid >> 5, lane = tid & 31;

    s_pre[tid]  = th_pre[tid];
    s_post[tid] = th_post[tid];

    for (int h = 0; h < HH; h++) {
        const float* src = dots + (((size_t)(b * HH + h) * Nq + i) * JJ);
        for (int j = tid; j < JJ; j += 256) sh[h * JJ + j] = src[j];
    }
    __syncthreads();

    float lmax[HH];
    #pragma unroll
    for (int g = 0; g < HH; g++) lmax[g] = -1e30f;
    for (int j = tid; j < JJ; j += 256) {
        float d[HH];
        #pragma unroll
        for (int h = 0; h < HH; h++) d[h] = sh[h * JJ + j];
        #pragma unroll
        for (int g = 0; g < HH; g++) {
            float m = 0.0f;
            #pragma unroll
            for (int h = 0; h < HH; h++) m = fmaf(s_pre[g * HH + h], d[h], m);
            sh[g * JJ + j] = m;
            lmax[g] = fmaxf(lmax[g], m);
        }
    }
    __syncthreads();
    #pragma unroll
    for (int g = 0; g < HH; g++) {
        float v = lmax[g];
        #pragma unroll
        for (int o = 16; o; o >>= 1) v = fmaxf(v, __shfl_xor_sync(0xffffffffu, v, o));
        if (lane == 0) red[g][warp] = v;
    }
    __syncthreads();
    if (tid < HH) {
        float v = red[tid][0];
        #pragma unroll
        for (int w = 1; w < 8; w++) v = fmaxf(v, red[tid][w]);
        gmax[tid] = v;
    }
    __syncthreads();

    float lsum[HH];
    #pragma unroll
    for (int g = 0; g < HH; g++) lsum[g] = 0.0f;
    for (int j = tid; j < JJ; j += 256) {
        #pragma unroll
        for (int g = 0; g < HH; g++) {
            float e = __expf(sh[g * JJ + j] - gmax[g]);
            sh[g * JJ + j] = e;
            lsum[g] += e;
        }
    }
    __syncthreads();
    #pragma unroll
    for (int g = 0; g < HH; g++) {
        float v = lsum[g];
        #pragma unroll
        for (int o = 16; o; o >>= 1) v += __shfl_xor_sync(0xffffffffu, v, o);
        if (lane == 0) red[g][warp] = v;
    }
    __syncthreads();
    if (tid < HH) {
        float v = 0.0f;
        #pragma unroll
        for (int w = 0; w < 8; w++) v += red[tid][w];
        gsum[tid] = v;
    }
    __syncthreads();
    Mmat[tid] = s_post[tid] / gsum[tid & 15];
    __syncthreads();

    for (int j = tid; j < JJP; j += 256) {
        float e[HH];
        bool in = (j < JJ);
        #pragma unroll
        for (int h = 0; h < HH; h++) e[h] = in ? sh[h * JJ + j] : 0.0f;
        #pragma unroll
        for (int g = 0; g < HH; g++) {
            float o = 0.0f;
            #pragma unroll
            for (int h = 0; h < HH; h++) o = fmaf(Mmat[g * HH + h], e[h], o);
            size_t oi = (((size_t)(b * HH + g) * Nq + i) * JJP) + j;
            __nv_bfloat16 oh, ol; split_bf16(o, oh, ol);
            atH[oi] = oh; atL[oi] = ol;
        }
    }
}

// ---------------- pre-split bf16x2 GEMM: 3-stage cp.async + ldmatrix --------
// A: [M][K] bf16 hi/lo row-major.  B: [Nc][K] bf16 hi/lo row-major (n-major).
// C = A @ B^T, fp32 accum via 3-term mma (loH + hiL + hiH). K % 32 == 0.

__device__ __forceinline__ void cp16(uint32_t dst, const void* src) {
    asm volatile("cp.async.ca.shared.global [%0], [%1], 16;" :: "r"(dst), "l"(src));
}
__device__ __forceinline__ void cpcommit() { asm volatile("cp.async.commit_group;"); }
template<int N> __device__ __forceinline__ void cpwait() {
    asm volatile("cp.async.wait_group %0;" :: "n"(N));
}

__device__ __forceinline__ void ldsm_x4(uint32_t& r0, uint32_t& r1, uint32_t& r2, uint32_t& r3,
                                        uint32_t addr) {
    asm volatile("ldmatrix.sync.aligned.m8n8.x4.shared.b16 {%0,%1,%2,%3}, [%4];"
                 : "=r"(r0), "=r"(r1), "=r"(r2), "=r"(r3) : "r"(addr));
}

__device__ __forceinline__ void mma_bf16(float* c, const uint32_t* a, const uint32_t* b) {
    asm volatile(
        "mma.sync.aligned.m16n8k16.row.col.f32.bf16.bf16.f32 "
        "{%0,%1,%2,%3}, {%4,%5,%6,%7}, {%8,%9}, {%0,%1,%2,%3};"
        : "+f"(c[0]), "+f"(c[1]), "+f"(c[2]), "+f"(c[3])
        : "r"(a[0]), "r"(a[1]), "r"(a[2]), "r"(a[3]),
          "r"(b[0]), "r"(b[1]));
}

template<int BM, int BN, int WM, int WN, bool GUARDN>
__global__ void __launch_bounds__((BM / WM) * (BN / WN) * 32)
psgemm_kernel(
    int M, int Nc, int K,
    const __nv_bfloat16* __restrict__ AH, const __nv_bfloat16* __restrict__ AL,
    long lda, long sA,
    const __nv_bfloat16* __restrict__ BH, const __nv_bfloat16* __restrict__ BL,
    long ldb, long sB,
    void* C0, void* C1, long sC,
    const float* __restrict__ alphaVec,
    float beta, int mode, int p1, int p2, int p3)
{
    constexpr int BK  = 32;
    constexpr int NTH = (BM / WM) * (BN / WN) * 32;
    constexpr int PA  = BK / 2 + 4;          // 20 u32 words pitch (A and B)
    constexpr int AW  = BM * PA;
    constexpr int BW  = BN * PA;
    constexpr int SW  = 2 * AW + 2 * BW;
    constexpr int MFR = WM / 16;
    constexpr int NFR = WN / 8;              // even (16-col B ldmatrix pairs)

    extern __shared__ uint32_t smem[];
    const uint32_t smem_addr = (uint32_t)__cvta_generic_to_shared(smem);

    const int z = blockIdx.z;
    const __nv_bfloat16* Ah = AH + (long)z * sA;
    const __nv_bfloat16* Al = AL + (long)z * sA;
    const __nv_bfloat16* Bh = BH + (long)z * sB;
    const __nv_bfloat16* Bl = BL + (long)z * sB;

    const int tid  = threadIdx.x;
    const int warp = tid >> 5;
    const int lane = tid & 31;
    const int g    = lane >> 2;
    const int tg   = lane & 3;
    const int wr   = warp / (BN / WN);
    const int wc   = warp % (BN / WN);
    const int rowBase = blockIdx.y * BM;
    const int colBase = blockIdx.x * BN;

    // ldmatrix lane geometry
    const int a_row  = (lane & 15);
    const int a_seg  = (lane >> 4) * 4;
    const int b_row  = (lane & 7) + ((lane >> 4) << 3);
    const int b_seg  = ((lane >> 3) & 1) * 4;

    float acc[MFR][NFR][4];
    #pragma unroll
    for (int i = 0; i < MFR; i++)
        #pragma unroll
        for (int j = 0; j < NFR; j++)
            #pragma unroll
            for (int q = 0; q < 4; q++) acc[i][j][q] = 0.0f;

    auto load_tile = [&](int stage, int k0) {
        uint32_t base = smem_addr + (uint32_t)stage * SW * 4;
        #pragma unroll 2
        for (int idx = tid; idx < BM * 4; idx += NTH) {
            int r  = idx >> 2;
            int c8 = idx & 3;
            long go = (long)(rowBase + r) * lda + k0 + c8 * 8;
            uint32_t d = base + (uint32_t)(r * PA + c8 * 4) * 4;
            cp16(d, Ah + go);
            cp16(d + AW * 4, Al + go);
        }
        #pragma unroll 2
        for (int idx = tid; idx < BN * 4; idx += NTH) {
            int c  = idx >> 2;
            int k8 = idx & 3;
            int gc = colBase + c;
            uint32_t d = base + (uint32_t)(2 * AW + c * PA + k8 * 4) * 4;
            if (!GUARDN || gc < Nc) {
                long go = (long)gc * ldb + k0 + k8 * 8;
                cp16(d, Bh + go);
                cp16(d + BW * 4, Bl + go);
            } else {
                uint4 zz = make_uint4(0, 0, 0, 0);
                *reinterpret_cast<uint4*>(&smem[stage * SW + 2 * AW + c * PA + k8 * 4]) = zz;
                *reinterpret_cast<uint4*>(&smem[stage * SW + 2 * AW + BW + c * PA + k8 * 4]) = zz;
            }
        }
    };

    // 3-stage pipeline, ONE __syncthreads per k-tile.
    // Invariant at iter kt (before this iter's commit): stage kt's cp.async
    // group is second-newest -> cpwait<1> guarantees it has landed. The write
    // target (kt+2)%3 was last read at iter kt-1, protected by this barrier.
    const int nK = K / BK;
    load_tile(0, 0);
    cpcommit();
    if (nK > 1) { load_tile(1, BK); cpcommit(); }

    for (int kt = 0; kt < nK; kt++) {
        cpwait<1>();
        __syncthreads();
        if (kt + 2 < nK) load_tile((kt + 2) % 3, (kt + 2) * BK);
        cpcommit();

        int cur = kt % 3;
        uint32_t baseB = smem_addr + (uint32_t)cur * SW * 4;
        uint32_t aH = baseB;
        uint32_t aL = baseB + AW * 4;
        uint32_t bH = baseB + 2 * AW * 4;
        uint32_t bL = bH + BW * 4;

        #pragma unroll
        for (int kk = 0; kk < BK; kk += 16) {
            const int kp = kk / 2;
            uint32_t afH[MFR][4], afL[MFR][4];
            uint32_t bfH[NFR][2], bfL[NFR][2];
            #pragma unroll
            for (int mi = 0; mi < MFR; mi++) {
                uint32_t off = (uint32_t)((wr * WM + mi * 16 + a_row) * PA + kp + a_seg) * 4;
                ldsm_x4(afH[mi][0], afH[mi][1], afH[mi][2], afH[mi][3], aH + off);
                ldsm_x4(afL[mi][0], afL[mi][1], afL[mi][2], afL[mi][3], aL + off);
            }
            #pragma unroll
            for (int np = 0; np < NFR / 2; np++) {
                uint32_t off = (uint32_t)((wc * WN + np * 16 + b_row) * PA + kp + b_seg) * 4;
                ldsm_x4(bfH[2*np][0], bfH[2*np][1], bfH[2*np+1][0], bfH[2*np+1][1], bH + off);
                ldsm_x4(bfL[2*np][0], bfL[2*np][1], bfL[2*np+1][0], bfL[2*np+1][1], bL + off);
            }
            #pragma unroll
            for (int mi = 0; mi < MFR; mi++)
                #pragma unroll
                for (int ni = 0; ni < NFR; ni++) {
                    float* c = acc[mi][ni];
                    mma_bf16(c, afL[mi], bfH[ni]);
                    mma_bf16(c, afH[mi], bfL[ni]);
                    mma_bf16(c, afH[mi], bfH[ni]);
                }
        }
    }

    float alpha = 1.0f;
    if (alphaVec) alpha = alphaVec[z % HH];

    #pragma unroll
    for (int mi = 0; mi < MFR; mi++) {
        #pragma unroll
        for (int half = 0; half < 2; half++) {
            int gr = rowBase + wr * WM + mi * 16 + g + half * 8;
            if (gr >= M) continue;
            #pragma unroll
            for (int ni = 0; ni < NFR; ni++) {
                #pragma unroll
                for (int e = 0; e < 2; e++) {
                    int gc = colBase + wc * WN + ni * 8 + tg * 2 + e;
                    if (gc >= Nc) continue;
                    float val = alpha * acc[mi][ni][half * 2 + e];
                    if (mode == 0) {
                        float* cp = (float*)C0 + (long)gr * p1 + gc;
                        *cp = (beta == 0.0f) ? val : fmaf(beta, *cp, val);
                    } else if (mode == 1) {
                        int b = gr / p1;
                        int rr = gr - b * p1;
                        int h = gc >> 6, d = gc & 63;
                        ((float*)C0)[(((long)(b * HH + h) * p2 + p3 + rr) << 6) + d] = val;
                    } else if (mode == 2) {
                        int b = z >> 4, h = z & 15;
                        long oi = (((long)(b * p1 + gr) * HH + h) << 6) + gc;
                        __nv_bfloat16 vh, vl; split_bf16(val, vh, vl);
                        ((__nv_bfloat16*)C0)[oi] = vh;
                        ((__nv_bfloat16*)C1)[oi] = vl;
                    } else if (mode == 3) {
                        ((float*)C0)[(long)z * sC + (long)gr * p1 + gc] = val;
                    } else {
                        int b = gr / p1;
                        int rr = gr - b * p1;
                        int h = gc >> 6, d = gc & 63;
                        long oi = ((long)(b * HH + h) * DHH + d) * JJP + NMEM + rr;
                        __nv_bfloat16 vh, vl; split_bf16(val, vh, vl);
                        ((__nv_bfloat16*)C0)[oi] = vh;
                        ((__nv_bfloat16*)C1)[oi] = vl;
                    }
                }
            }
        }
    }
}

// ---------------- host launch ------------------------------------------------

static constexpr size_t MIX_SMEM  = (size_t)HH * JJ * sizeof(float);        // 132096
static constexpr int    BIG_SMEM  = 3 * (2 * 128 * 20 + 2 * 128 * 20) * 4;  // 122880
static constexpr int    SML_SMEM  = 3 * (2 * 64 * 20 + 2 * 64 * 20) * 4;    // 61440

extern "C" void kernel_launch(void* const* d_in, const int* in_sizes, int n_in,
                              void* d_out, int out_size)
{
    (void)in_sizes; (void)n_in; (void)out_size;
    const float* x   = (const float*)d_in[0];
    const float* ctx = (const float*)d_in[1];
    const float* wq[2]     = {(const float*)d_in[2],  (const float*)d_in[5]};
    const float* wk[2]     = {(const float*)d_in[3],  (const float*)d_in[6]};
    const float* wv[2]     = {(const float*)d_in[4],  (const float*)d_in[7]};
    const float* thpre[2]  = {(const float*)d_in[8],  (const float*)d_in[10]};
    const float* thpost[2] = {(const float*)d_in[9],  (const float*)d_in[11]};
    const float* scp[2]    = {(const float*)d_in[12], (const float*)d_in[13]};
    const float* mk[2]     = {(const float*)d_in[14], (const float*)d_in[16]};
    const float* mv[2]     = {(const float*)d_in[15], (const float*)d_in[17]};
    const float* hs[2]     = {(const float*)d_in[18], (const float*)d_in[19]};
    const float* wo[2]     = {(const float*)d_in[20], (const float*)d_in[21]};
    float* out = (float*)d_out;

    float *qn, *kn, *dots, *scl;
    __nv_bfloat16 *xH,*xL,*cH,*cL,*wTH,*wTL,*qnH,*qnL,*knH,*knL,*vTH,*vTL,*atH,*atL,*ctH,*ctL;
    cudaGetSymbolAddress((void**)&qn,   g_qn);
    cudaGetSymbolAddress((void**)&kn,   g_kn);
    cudaGetSymbolAddress((void**)&dots, g_dots);
    cudaGetSymbolAddress((void**)&scl,  g_scale);
    cudaGetSymbolAddress((void**)&xH,  g_xH);  cudaGetSymbolAddress((void**)&xL,  g_xL);
    cudaGetSymbolAddress((void**)&cH,  g_cH);  cudaGetSymbolAddress((void**)&cL,  g_cL);
    cudaGetSymbolAddress((void**)&wTH, g_wTH); cudaGetSymbolAddress((void**)&wTL, g_wTL);
    cudaGetSymbolAddress((void**)&qnH, g_qnH); cudaGetSymbolAddress((void**)&qnL, g_qnL);
    cudaGetSymbolAddress((void**)&knH, g_knH); cudaGetSymbolAddress((void**)&knL, g_knL);
    cudaGetSymbolAddress((void**)&vTH, g_vTH); cudaGetSymbolAddress((void**)&vTL, g_vTL);
    cudaGetSymbolAddress((void**)&atH, g_atH); cudaGetSymbolAddress((void**)&atL, g_atL);
    cudaGetSymbolAddress((void**)&ctH, g_ctH); cudaGetSymbolAddress((void**)&ctL, g_ctL);

    auto projk = psgemm_kernel<128, 128, 64, 32, false>;
    auto dotsk = psgemm_kernel<128, 128, 64, 32, true>;
    auto avk   = psgemm_kernel<64, 64, 32, 32, false>;
    cudaFuncSetAttribute(projk, cudaFuncAttributeMaxDynamicSharedMemorySize, BIG_SMEM);
    cudaFuncSetAttribute(dotsk, cudaFuncAttributeMaxDynamicSharedMemorySize, BIG_SMEM);
    cudaFuncSetAttribute(avk,   cudaFuncAttributeMaxDynamicSharedMemorySize, SML_SMEM);
    cudaFuncSetAttribute(mix_softmax_kernel,
                         cudaFuncAttributeMaxDynamicSharedMemorySize, (int)MIX_SMEM);

    // split x once (shared by both layers)
    split_kernel<<<(Bc * Nq * DIM / 4 + 255) / 256, 256>>>(xH, xL, x, (long)Bc * Nq * DIM / 4);

    for (int l = 0; l < 2; l++) {
        scale_kernel<<<1, 16>>>(scl, scp[l]);

        split_kernel<<<(Bc * NCTX * DIM / 4 + 255) / 256, 256>>>(
            cH, cL, ctx + (size_t)l * Bc * NCTX * DIM, (long)Bc * NCTX * DIM / 4);

        // Q = x @ wq -> qn fp32 [b,h,n,d]
        tconv_kernel<<<dim3(HDH / 32, DIM / 32), dim3(32, 8)>>>(wTH, wTL, wq[l], DIM, HDH);
        projk<<<dim3(8, 16, 1), 256, BIG_SMEM>>>(
            Bc * Nq, HDH, DIM, xH, xL, DIM, 0, wTH, wTL, DIM, 0,
            qn, nullptr, 0, nullptr, 0.0f, 1, Nq, Nq, 0);

        // K = ctx @ wk -> kn fp32 rows [NMEM..JJ)
        tconv_kernel<<<dim3(HDH / 32, DIM / 32), dim3(32, 8)>>>(wTH, wTL, wk[l], DIM, HDH);
        projk<<<dim3(8, 32, 1), 256, BIG_SMEM>>>(
            Bc * NCTX, HDH, DIM, cH, cL, DIM, 0, wTH, wTL, DIM, 0,
            kn, nullptr, 0, nullptr, 0.0f, 1, NCTX, JJ, NMEM);

        // V = ctx @ wv -> vT split bf16, rows [NMEM..JJ)
        tconv_kernel<<<dim3(HDH / 32, DIM / 32), dim3(32, 8)>>>(wTH, wTL, wv[l], DIM, HDH);
        projk<<<dim3(8, 32, 1), 256, BIG_SMEM>>>(
            Bc * NCTX, HDH, DIM, cH, cL, DIM, 0, wTH, wTL, DIM, 0,
            vTH, vTL, 0, nullptr, 0.0f, 4, NCTX, 0, 0);

        memfill_kernel<<<64, 256>>>(kn, vTH, vTL, mk[l], mv[l]);

        l2norm_split_kernel<<<(Bc * HH * Nq + 7) / 8, 256>>>(qn, qnH, qnL, Bc * HH * Nq);
        l2norm_split_kernel<<<(Bc * HH * JJ + 7) / 8, 256>>>(kn, knH, knL, Bc * HH * JJ);

        // dots = scale[h] * qn @ kn^T  (z = b*16+h), fp32 out
        dotsk<<<dim3(17, 8, 32), 256, BIG_SMEM>>>(
            Nq, JJ, DHH, qnH, qnL, DHH, (long)Nq * DHH,
            knH, knL, DHH, (long)JJ * DHH,
            dots, nullptr, (long)Nq * JJ, scl, 0.0f, 3, JJ, 0, 0);

        // talking-heads mix + softmax -> attn split bf16 (pitch JJP)
        mix_softmax_kernel<<<Bc * Nq, 256, MIX_SMEM>>>(dots, atH, atL, thpre[l], thpost[l]);

        // out_heads = hs[h] * attn @ v -> cat split bf16 [b,n,(h,d)]
        avk<<<dim3(1, 16, 32), 128, SML_SMEM>>>(
            Nq, DHH, JJP, atH, atL, JJP, (long)Nq * JJP,
            vTH, vTL, JJP, (long)DHH * JJP,
            ctH, ctL, 0, hs[l], 0.0f, 2, Nq, 0, 0);

        // out (+)= cat @ wo
        tconv_kernel<<<dim3(DIM / 32, HDH / 32), dim3(32, 8)>>>(wTH, wTL, wo[l], HDH, DIM);
        projk<<<dim3(8, 16, 1), 256, BIG_SMEM>>>(
            Bc * Nq, DIM, HDH, ctH, ctL, HDH, 0, wTH, wTL, HDH, 0,
            out, nullptr, 0, nullptr, (l == 0 ? 0.0f : 1.0f), 0, DIM, 0, 0);
    }
}

// round 16
// speedup vs baseline: 1.1597x; 1.0387x over previous
#include <cuda_runtime.h>
#include <cuda_bf16.h>
#include <math.h>
#include <stdint.h>

// Problem constants
#define HH 16
#define DHH 64
static constexpr int Bc   = 2;
static constexpr int Nq   = 1024;
static constexpr int NCTX = 2048;
static constexpr int DIM  = 1024;
static constexpr int NMEM = 16;
static constexpr int JJ   = NCTX + NMEM;   // 2064
static constexpr int JJP  = 2080;          // padded to multiple of 32 (BK)
static constexpr int HDH  = HH * DHH;      // 1024

// per-layer element counts
static constexpr size_t S_W    = (size_t)HDH * DIM;          // one weight matrix
static constexpr size_t QN_L   = (size_t)Bc * HH * Nq * DHH;
static constexpr size_t KN_L   = (size_t)Bc * HH * JJ * DHH;
static constexpr size_t VT_L   = (size_t)Bc * HH * DHH * JJP;
static constexpr size_t AT_L   = (size_t)Bc * HH * Nq * (size_t)JJP;
static constexpr size_t CT_L   = (size_t)Bc * Nq * HDH;
static constexpr size_t DOTS_L = (size_t)Bc * HH * Nq * (size_t)JJ;
static constexpr size_t OA_L   = (size_t)Bc * Nq * DIM;

// ---------------- scratch (device globals; both layers) ----------------------
__device__ float g_qn[2 * QN_L];
__device__ float g_kn[2 * KN_L];
__device__ float g_dots[2 * DOTS_L];
__device__ float g_oacc[2 * OA_L];
__device__ float g_scale[32];   // [l][h]
__device__ float g_hs[32];      // [l][h]

__device__ __align__(16) __nv_bfloat16 g_xH [(size_t)Bc * Nq * DIM];
__device__ __align__(16) __nv_bfloat16 g_xL [(size_t)Bc * Nq * DIM];
__device__ __align__(16) __nv_bfloat16 g_cH [2 * (size_t)Bc * NCTX * DIM];
__device__ __align__(16) __nv_bfloat16 g_cL [2 * (size_t)Bc * NCTX * DIM];
__device__ __align__(16) __nv_bfloat16 g_wTH[8 * S_W];   // q0,q1,k0,k1,v0,v1,o0,o1
__device__ __align__(16) __nv_bfloat16 g_wTL[8 * S_W];
__device__ __align__(16) __nv_bfloat16 g_qnH[2 * QN_L];
__device__ __align__(16) __nv_bfloat16 g_qnL[2 * QN_L];
__device__ __align__(16) __nv_bfloat16 g_knH[2 * KN_L];
__device__ __align__(16) __nv_bfloat16 g_knL[2 * KN_L];
__device__ __align__(16) __nv_bfloat16 g_vTH[2 * VT_L];
__device__ __align__(16) __nv_bfloat16 g_vTL[2 * VT_L];
__device__ __align__(16) __nv_bfloat16 g_atH[2 * AT_L];
__device__ __align__(16) __nv_bfloat16 g_atL[2 * AT_L];
__device__ __align__(16) __nv_bfloat16 g_ctH[2 * CT_L];
__device__ __align__(16) __nv_bfloat16 g_ctL[2 * CT_L];

// ---------------- split helpers ---------------------------------------------
__device__ __forceinline__ uint32_t pack_bf2(__nv_bfloat16 a, __nv_bfloat16 b) {
    return ((uint32_t)__bfloat16_as_ushort(b) << 16) | (uint32_t)__bfloat16_as_ushort(a);
}
__device__ __forceinline__ void split_bf16(float x, __nv_bfloat16& h, __nv_bfloat16& l) {
    h = __float2bfloat16(x);
    l = __float2bfloat16(x - __bfloat162float(h));
}

// ---------------- tiny kernels ----------------------------------------------

// scl[l*16+h] = 1/max(exp(p),0.01);  hsbuf[l*16+h] = hs
__global__ void prep_kernel(float* __restrict__ scl, float* __restrict__ hsb,
                            const float* __restrict__ p0, const float* __restrict__ p1,
                            const float* __restrict__ h0, const float* __restrict__ h1) {
    int t = threadIdx.x;           // 0..31
    int h = t & 15, l = t >> 4;
    const float* p = l ? p1 : p0;
    const float* hv = l ? h1 : h0;
    scl[t] = 1.0f / fmaxf(expf(p[h]), 0.01f);
    hsb[t] = hv[h];
}

__global__ void split_kernel(__nv_bfloat16* __restrict__ H, __nv_bfloat16* __restrict__ L,
                             const float* __restrict__ src, long n4) {
    long i = blockIdx.x * (long)blockDim.x + threadIdx.x;
    if (i >= n4) return;
    float4 v = reinterpret_cast<const float4*>(src)[i];
    __nv_bfloat16 h0,l0,h1,l1,h2,l2,h3,l3;
    split_bf16(v.x,h0,l0); split_bf16(v.y,h1,l1);
    split_bf16(v.z,h2,l2); split_bf16(v.w,h3,l3);
    reinterpret_cast<uint2*>(H)[i] = make_uint2(pack_bf2(h0,h1), pack_bf2(h2,h3));
    reinterpret_cast<uint2*>(L)[i] = make_uint2(pack_bf2(l0,l1), pack_bf2(l2,l3));
}

// transpose + split: src [K][N] fp32 -> dst[n][k] bf16 hi/lo
__global__ void tconv_kernel(__nv_bfloat16* __restrict__ H, __nv_bfloat16* __restrict__ L,
                             const float* __restrict__ src, int K, int N) {
    __shared__ float t[32][33];
    int n0 = blockIdx.x * 32, k0 = blockIdx.y * 32;
    for (int yy = threadIdx.y; yy < 32; yy += 8)
        t[yy][threadIdx.x] = src[(long)(k0 + yy) * N + n0 + threadIdx.x];
    __syncthreads();
    for (int yy = threadIdx.y; yy < 32; yy += 8) {
        float v = t[threadIdx.x][yy];
        long o = (long)(n0 + yy) * K + k0 + threadIdx.x;
        __nv_bfloat16 h, l; split_bf16(v, h, l);
        H[o] = h; L[o] = l;
    }
}

// memory K rows + transposed memory V cols for BOTH layers; zero vT pads
__global__ void memfill_kernel(float* __restrict__ kn,
                               __nv_bfloat16* __restrict__ vTH, __nv_bfloat16* __restrict__ vTL,
                               const float* __restrict__ mk0, const float* __restrict__ mv0,
                               const float* __restrict__ mk1, const float* __restrict__ mv1) {
    int idx = blockIdx.x * blockDim.x + threadIdx.x;
    const int total = HH * NMEM * DHH;
    if (idx >= total) return;
    int h   = idx / (NMEM * DHH);
    int rem = idx % (NMEM * DHH);
    int m = rem / DHH, d = rem % DHH;
    for (int l = 0; l < 2; l++) {
        float k = (l ? mk1 : mk0)[idx];
        float v = (l ? mv1 : mv0)[idx];
        __nv_bfloat16 vh, vl; split_bf16(v, vh, vl);
        for (int b = 0; b < Bc; b++) {
            kn[(size_t)l * KN_L + (((size_t)(b * HH + h) * JJ) + m) * DHH + d] = k;
            size_t base = (size_t)l * VT_L + ((size_t)(b * HH + h) * DHH + d) * JJP;
            vTH[base + m] = vh;            vTL[base + m] = vl;
            vTH[base + JJ + m] = __float2bfloat16(0.f);
            vTL[base + JJ + m] = __float2bfloat16(0.f);
        }
    }
}

__global__ void l2norm_split_kernel(const float* __restrict__ src,
                                    __nv_bfloat16* __restrict__ H,
                                    __nv_bfloat16* __restrict__ L, int rows) {
    int row = blockIdx.x * 8 + (threadIdx.x >> 5);
    if (row >= rows) return;
    int lane = threadIdx.x & 31;
    float2 v = reinterpret_cast<const float2*>(src + (size_t)row * DHH)[lane];
    float ss = v.x * v.x + v.y * v.y;
    #pragma unroll
    for (int o = 16; o; o >>= 1) ss += __shfl_xor_sync(0xffffffffu, ss, o);
    float inv = 1.0f / fmaxf(sqrtf(ss), 1e-12f);
    __nv_bfloat16 hx,lx,hy,ly;
    split_bf16(v.x * inv, hx, lx);
    split_bf16(v.y * inv, hy, ly);
    reinterpret_cast<uint32_t*>(H)[(size_t)row * 32 + lane] = pack_bf2(hx, hy);
    reinterpret_cast<uint32_t*>(L)[(size_t)row * 32 + lane] = pack_bf2(lx, ly);
}

__global__ void add_kernel(float* __restrict__ out, const float* __restrict__ oa, long n4) {
    long i = blockIdx.x * (long)blockDim.x + threadIdx.x;
    if (i >= n4) return;
    float4 a = reinterpret_cast<const float4*>(oa)[i];
    float4 b = reinterpret_cast<const float4*>(oa + OA_L)[i];
    reinterpret_cast<float4*>(out)[i] =
        make_float4(a.x + b.x, a.y + b.y, a.z + b.z, a.w + b.w);
}

// ---------------- fused talking-heads pre-mix + softmax + post-mix ----------
// both layers: blockIdx.x in [0, 2*Bc*Nq)
__global__ void mix_softmax_kernel(const float* __restrict__ dots,
                                   __nv_bfloat16* __restrict__ atH,
                                   __nv_bfloat16* __restrict__ atL,
                                   const float* __restrict__ pre0,
                                   const float* __restrict__ post0,
                                   const float* __restrict__ pre1,
                                   const float* __restrict__ post1) {
    extern __shared__ float sh[];
    __shared__ float s_pre[HH * HH], s_post[HH * HH];
    __shared__ float red[HH][8];
    __shared__ float gmax[HH], gsum[HH], Mmat[HH * HH];

    const int l  = blockIdx.x / (Bc * Nq);
    const int bi = blockIdx.x % (Bc * Nq);
    const int b = bi / Nq, i = bi % Nq;
    const int tid = threadIdx.x;
    const int warp = tid >> 5, lane = tid & 31;

    const float* th_pre  = l ? pre1  : pre0;
    const float* th_post = l ? post1 : post0;
    dots += (size_t)l * DOTS_L;
    atH  += (size_t)l * AT_L;
    atL  += (size_t)l * AT_L;

    s_pre[tid]  = th_pre[tid];
    s_post[tid] = th_post[tid];

    for (int h = 0; h < HH; h++) {
        const float* src = dots + (((size_t)(b * HH + h) * Nq + i) * JJ);
        for (int j = tid; j < JJ; j += 256) sh[h * JJ + j] = src[j];
    }
    __syncthreads();

    float lmax[HH];
    #pragma unroll
    for (int g = 0; g < HH; g++) lmax[g] = -1e30f;
    for (int j = tid; j < JJ; j += 256) {
        float d[HH];
        #pragma unroll
        for (int h = 0; h < HH; h++) d[h] = sh[h * JJ + j];
        #pragma unroll
        for (int g = 0; g < HH; g++) {
            float m = 0.0f;
            #pragma unroll
            for (int h = 0; h < HH; h++) m = fmaf(s_pre[g * HH + h], d[h], m);
            sh[g * JJ + j] = m;
            lmax[g] = fmaxf(lmax[g], m);
        }
    }
    __syncthreads();
    #pragma unroll
    for (int g = 0; g < HH; g++) {
        float v = lmax[g];
        #pragma unroll
        for (int o = 16; o; o >>= 1) v = fmaxf(v, __shfl_xor_sync(0xffffffffu, v, o));
        if (lane == 0) red[g][warp] = v;
    }
    __syncthreads();
    if (tid < HH) {
        float v = red[tid][0];
        #pragma unroll
        for (int w = 1; w < 8; w++) v = fmaxf(v, red[tid][w]);
        gmax[tid] = v;
    }
    __syncthreads();

    float lsum[HH];
    #pragma unroll
    for (int g = 0; g < HH; g++) lsum[g] = 0.0f;
    for (int j = tid; j < JJ; j += 256) {
        #pragma unroll
        for (int g = 0; g < HH; g++) {
            float e = __expf(sh[g * JJ + j] - gmax[g]);
            sh[g * JJ + j] = e;
            lsum[g] += e;
        }
    }
    __syncthreads();
    #pragma unroll
    for (int g = 0; g < HH; g++) {
        float v = lsum[g];
        #pragma unroll
        for (int o = 16; o; o >>= 1) v += __shfl_xor_sync(0xffffffffu, v, o);
        if (lane == 0) red[g][warp] = v;
    }
    __syncthreads();
    if (tid < HH) {
        float v = 0.0f;
        #pragma unroll
        for (int w = 0; w < 8; w++) v += red[tid][w];
        gsum[tid] = v;
    }
    __syncthreads();
    Mmat[tid] = s_post[tid] / gsum[tid & 15];
    __syncthreads();

    for (int j = tid; j < JJP; j += 256) {
        float e[HH];
        bool in = (j < JJ);
        #pragma unroll
        for (int h = 0; h < HH; h++) e[h] = in ? sh[h * JJ + j] : 0.0f;
        #pragma unroll
        for (int g = 0; g < HH; g++) {
            float o = 0.0f;
            #pragma unroll
            for (int h = 0; h < HH; h++) o = fmaf(Mmat[g * HH + h], e[h], o);
            size_t oi = (((size_t)(b * HH + g) * Nq + i) * JJP) + j;
            __nv_bfloat16 oh, ol; split_bf16(o, oh, ol);
            atH[oi] = oh; atL[oi] = ol;
        }
    }
}

// ---------------- pre-split bf16x2 GEMM: 3-stage cp.async + ldmatrix --------
// A: [M][K] bf16 hi/lo row-major.  B: [Nc][K] bf16 hi/lo row-major (n-major).
// C = A @ B^T, fp32 accum via 3-term mma (loH + hiL + hiH). K % 32 == 0.
// All outputs offset by z (modes 1/3/4: z*sC; mode 2: (z>>5)*sC).
// alphaVec (if set) indexed by ((z>>5)<<4)|(z&15)  = [l][h].

__device__ __forceinline__ void cp16(uint32_t dst, const void* src) {
    asm volatile("cp.async.ca.shared.global [%0], [%1], 16;" :: "r"(dst), "l"(src));
}
__device__ __forceinline__ void cpcommit() { asm volatile("cp.async.commit_group;"); }
template<int N> __device__ __forceinline__ void cpwait() {
    asm volatile("cp.async.wait_group %0;" :: "n"(N));
}

__device__ __forceinline__ void ldsm_x4(uint32_t& r0, uint32_t& r1, uint32_t& r2, uint32_t& r3,
                                        uint32_t addr) {
    asm volatile("ldmatrix.sync.aligned.m8n8.x4.shared.b16 {%0,%1,%2,%3}, [%4];"
                 : "=r"(r0), "=r"(r1), "=r"(r2), "=r"(r3) : "r"(addr));
}

__device__ __forceinline__ void mma_bf16(float* c, const uint32_t* a, const uint32_t* b) {
    asm volatile(
        "mma.sync.aligned.m16n8k16.row.col.f32.bf16.bf16.f32 "
        "{%0,%1,%2,%3}, {%4,%5,%6,%7}, {%8,%9}, {%0,%1,%2,%3};"
        : "+f"(c[0]), "+f"(c[1]), "+f"(c[2]), "+f"(c[3])
        : "r"(a[0]), "r"(a[1]), "r"(a[2]), "r"(a[3]),
          "r"(b[0]), "r"(b[1]));
}

template<int BM, int BN, int WM, int WN, bool GUARDN>
__global__ void __launch_bounds__((BM / WM) * (BN / WN) * 32)
psgemm_kernel(
    int M, int Nc, int K,
    const __nv_bfloat16* __restrict__ AH, const __nv_bfloat16* __restrict__ AL,
    long lda, long sA,
    const __nv_bfloat16* __restrict__ BH, const __nv_bfloat16* __restrict__ BL,
    long ldb, long sB,
    void* C0, void* C1, long sC,
    const float* __restrict__ alphaVec,
    float beta, int mode, int p1, int p2, int p3)
{
    constexpr int BK  = 32;
    constexpr int NTH = (BM / WM) * (BN / WN) * 32;
    constexpr int PA  = BK / 2 + 4;
    constexpr int AW  = BM * PA;
    constexpr int BW  = BN * PA;
    constexpr int SW  = 2 * AW + 2 * BW;
    constexpr int MFR = WM / 16;
    constexpr int NFR = WN / 8;

    extern __shared__ uint32_t smem[];
    const uint32_t smem_addr = (uint32_t)__cvta_generic_to_shared(smem);

    const int z = blockIdx.z;
    const __nv_bfloat16* Ah = AH + (long)z * sA;
    const __nv_bfloat16* Al = AL + (long)z * sA;
    const __nv_bfloat16* Bh = BH + (long)z * sB;
    const __nv_bfloat16* Bl = BL + (long)z * sB;

    const int tid  = threadIdx.x;
    const int warp = tid >> 5;
    const int lane = tid & 31;
    const int g    = lane >> 2;
    const int tg   = lane & 3;
    const int wr   = warp / (BN / WN);
    const int wc   = warp % (BN / WN);
    const int rowBase = blockIdx.y * BM;
    const int colBase = blockIdx.x * BN;

    const int a_row  = (lane & 15);
    const int a_seg  = (lane >> 4) * 4;
    const int b_row  = (lane & 7) + ((lane >> 4) << 3);
    const int b_seg  = ((lane >> 3) & 1) * 4;

    float acc[MFR][NFR][4];
    #pragma unroll
    for (int i = 0; i < MFR; i++)
        #pragma unroll
        for (int j = 0; j < NFR; j++)
            #pragma unroll
            for (int q = 0; q < 4; q++) acc[i][j][q] = 0.0f;

    auto load_tile = [&](int stage, int k0) {
        uint32_t base = smem_addr + (uint32_t)stage * SW * 4;
        #pragma unroll 2
        for (int idx = tid; idx < BM * 4; idx += NTH) {
            int r  = idx >> 2;
            int c8 = idx & 3;
            long go = (long)(rowBase + r) * lda + k0 + c8 * 8;
            uint32_t d = base + (uint32_t)(r * PA + c8 * 4) * 4;
            cp16(d, Ah + go);
            cp16(d + AW * 4, Al + go);
        }
        #pragma unroll 2
        for (int idx = tid; idx < BN * 4; idx += NTH) {
            int c  = idx >> 2;
            int k8 = idx & 3;
            int gc = colBase + c;
            uint32_t d = base + (uint32_t)(2 * AW + c * PA + k8 * 4) * 4;
            if (!GUARDN || gc < Nc) {
                long go = (long)gc * ldb + k0 + k8 * 8;
                cp16(d, Bh + go);
                cp16(d + BW * 4, Bl + go);
            } else {
                uint4 zz = make_uint4(0, 0, 0, 0);
                *reinterpret_cast<uint4*>(&smem[stage * SW + 2 * AW + c * PA + k8 * 4]) = zz;
                *reinterpret_cast<uint4*>(&smem[stage * SW + 2 * AW + BW + c * PA + k8 * 4]) = zz;
            }
        }
    };

    const int nK = K / BK;
    load_tile(0, 0);
    cpcommit();
    if (nK > 1) { load_tile(1, BK); cpcommit(); }

    for (int kt = 0; kt < nK; kt++) {
        cpwait<1>();
        __syncthreads();
        if (kt + 2 < nK) load_tile((kt + 2) % 3, (kt + 2) * BK);
        cpcommit();

        int cur = kt % 3;
        uint32_t baseB = smem_addr + (uint32_t)cur * SW * 4;
        uint32_t aH = baseB;
        uint32_t aL = baseB + AW * 4;
        uint32_t bH = baseB + 2 * AW * 4;
        uint32_t bL = bH + BW * 4;

        #pragma unroll
        for (int kk = 0; kk < BK; kk += 16) {
            const int kp = kk / 2;
            uint32_t afH[MFR][4], afL[MFR][4];
            uint32_t bfH[NFR][2], bfL[NFR][2];
            #pragma unroll
            for (int mi = 0; mi < MFR; mi++) {
                uint32_t off = (uint32_t)((wr * WM + mi * 16 + a_row) * PA + kp + a_seg) * 4;
                ldsm_x4(afH[mi][0], afH[mi][1], afH[mi][2], afH[mi][3], aH + off);
                ldsm_x4(afL[mi][0], afL[mi][1], afL[mi][2], afL[mi][3], aL + off);
            }
            #pragma unroll
            for (int np = 0; np < NFR / 2; np++) {
                uint32_t off = (uint32_t)((wc * WN + np * 16 + b_row) * PA + kp + b_seg) * 4;
                ldsm_x4(bfH[2*np][0], bfH[2*np][1], bfH[2*np+1][0], bfH[2*np+1][1], bH + off);
                ldsm_x4(bfL[2*np][0], bfL[2*np][1], bfL[2*np+1][0], bfL[2*np+1][1], bL + off);
            }
            #pragma unroll
            for (int mi = 0; mi < MFR; mi++)
                #pragma unroll
                for (int ni = 0; ni < NFR; ni++) {
                    float* c = acc[mi][ni];
                    mma_bf16(c, afL[mi], bfH[ni]);
                    mma_bf16(c, afH[mi], bfL[ni]);
                    mma_bf16(c, afH[mi], bfH[ni]);
                }
        }
    }

    float alpha = 1.0f;
    if (alphaVec) alpha = alphaVec[((z >> 5) << 4) | (z & 15)];

    #pragma unroll
    for (int mi = 0; mi < MFR; mi++) {
        #pragma unroll
        for (int half = 0; half < 2; half++) {
            int gr = rowBase + wr * WM + mi * 16 + g + half * 8;
            if (gr >= M) continue;
            #pragma unroll
            for (int ni = 0; ni < NFR; ni++) {
                #pragma unroll
                for (int e = 0; e < 2; e++) {
                    int gc = colBase + wc * WN + ni * 8 + tg * 2 + e;
                    if (gc >= Nc) continue;
                    float val = alpha * acc[mi][ni][half * 2 + e];
                    if (mode == 0) {
                        float* cp = (float*)C0 + (long)z * sC + (long)gr * p1 + gc;
                        *cp = (beta == 0.0f) ? val : fmaf(beta, *cp, val);
                    } else if (mode == 1) {               // split-heads fp32
                        int b = gr / p1;
                        int rr = gr - b * p1;
                        int h = gc >> 6, d = gc & 63;
                        ((float*)C0)[(long)z * sC +
                            (((long)(b * HH + h) * p2 + p3 + rr) << 6) + d] = val;
                    } else if (mode == 2) {               // cat split bf16 (z=l*32+b*16+h)
                        int b = (z >> 4) & 1, h = z & 15;
                        long oi = (long)(z >> 5) * sC + (((long)(b * p1 + gr) * HH + h) << 6) + gc;
                        __nv_bfloat16 vh, vl; split_bf16(val, vh, vl);
                        ((__nv_bfloat16*)C0)[oi] = vh;
                        ((__nv_bfloat16*)C1)[oi] = vl;
                    } else if (mode == 3) {               // batched plain fp32
                        ((float*)C0)[(long)z * sC + (long)gr * p1 + gc] = val;
                    } else {                              // mode 4: vT split bf16 (z=l)
                        int b = gr / p1;
                        int rr = gr - b * p1;
                        int h = gc >> 6, d = gc & 63;
                        long oi = (long)z * sC +
                                  ((long)(b * HH + h) * DHH + d) * JJP + NMEM + rr;
                        __nv_bfloat16 vh, vl; split_bf16(val, vh, vl);
                        ((__nv_bfloat16*)C0)[oi] = vh;
                        ((__nv_bfloat16*)C1)[oi] = vl;
                    }
                }
            }
        }
    }
}

// ---------------- host launch ------------------------------------------------

static constexpr size_t MIX_SMEM  = (size_t)HH * JJ * sizeof(float);        // 132096
static constexpr int    BIG_SMEM  = 3 * (2 * 128 * 20 + 2 * 128 * 20) * 4;  // 122880
static constexpr int    SML_SMEM  = 3 * (2 * 64 * 20 + 2 * 64 * 20) * 4;    // 61440

extern "C" void kernel_launch(void* const* d_in, const int* in_sizes, int n_in,
                              void* d_out, int out_size)
{
    (void)in_sizes; (void)n_in; (void)out_size;
    const float* x   = (const float*)d_in[0];
    const float* ctx = (const float*)d_in[1];
    const float* wq[2]     = {(const float*)d_in[2],  (const float*)d_in[5]};
    const float* wk[2]     = {(const float*)d_in[3],  (const float*)d_in[6]};
    const float* wv[2]     = {(const float*)d_in[4],  (const float*)d_in[7]};
    const float* thpre[2]  = {(const float*)d_in[8],  (const float*)d_in[10]};
    const float* thpost[2] = {(const float*)d_in[9],  (const float*)d_in[11]};
    const float* scp[2]    = {(const float*)d_in[12], (const float*)d_in[13]};
    const float* mk[2]     = {(const float*)d_in[14], (const float*)d_in[16]};
    const float* mv[2]     = {(const float*)d_in[15], (const float*)d_in[17]};
    const float* hs[2]     = {(const float*)d_in[18], (const float*)d_in[19]};
    const float* wo[2]     = {(const float*)d_in[20], (const float*)d_in[21]};
    float* out = (float*)d_out;

    float *qn, *kn, *dots, *scl, *hsb, *oacc;
    __nv_bfloat16 *xH,*xL,*cH,*cL,*wTH,*wTL,*qnH,*qnL,*knH,*knL,*vTH,*vTL,*atH,*atL,*ctH,*ctL;
    cudaGetSymbolAddress((void**)&qn,   g_qn);
    cudaGetSymbolAddress((void**)&kn,   g_kn);
    cudaGetSymbolAddress((void**)&dots, g_dots);
    cudaGetSymbolAddress((void**)&scl,  g_scale);
    cudaGetSymbolAddress((void**)&hsb,  g_hs);
    cudaGetSymbolAddress((void**)&oacc, g_oacc);
    cudaGetSymbolAddress((void**)&xH,  g_xH);  cudaGetSymbolAddress((void**)&xL,  g_xL);
    cudaGetSymbolAddress((void**)&cH,  g_cH);  cudaGetSymbolAddress((void**)&cL,  g_cL);
    cudaGetSymbolAddress((void**)&wTH, g_wTH); cudaGetSymbolAddress((void**)&wTL, g_wTL);
    cudaGetSymbolAddress((void**)&qnH, g_qnH); cudaGetSymbolAddress((void**)&qnL, g_qnL);
    cudaGetSymbolAddress((void**)&knH, g_knH); cudaGetSymbolAddress((void**)&knL, g_knL);
    cudaGetSymbolAddress((void**)&vTH, g_vTH); cudaGetSymbolAddress((void**)&vTL, g_vTL);
    cudaGetSymbolAddress((void**)&atH, g_atH); cudaGetSymbolAddress((void**)&atL, g_atL);
    cudaGetSymbolAddress((void**)&ctH, g_ctH); cudaGetSymbolAddress((void**)&ctL, g_ctL);

    auto projk = psgemm_kernel<128, 128, 64, 32, false>;
    auto dotsk = psgemm_kernel<128, 128, 64, 32, true>;
    auto avk   = psgemm_kernel<64, 64, 32, 32, false>;
    cudaFuncSetAttribute(projk, cudaFuncAttributeMaxDynamicSharedMemorySize, BIG_SMEM);
    cudaFuncSetAttribute(dotsk, cudaFuncAttributeMaxDynamicSharedMemorySize, BIG_SMEM);
    cudaFuncSetAttribute(avk,   cudaFuncAttributeMaxDynamicSharedMemorySize, SML_SMEM);
    cudaFuncSetAttribute(mix_softmax_kernel,
                         cudaFuncAttributeMaxDynamicSharedMemorySize, (int)MIX_SMEM);

    // ---- prologue: scales, weight transposes, input splits ----
    prep_kernel<<<1, 32>>>(scl, hsb, scp[0], scp[1], hs[0], hs[1]);

    dim3 tgrid(HDH / 32, DIM / 32), tblk(32, 8);
    for (int l = 0; l < 2; l++) {
        tconv_kernel<<<tgrid, tblk>>>(wTH + (0 * 2 + l) * S_W, wTL + (0 * 2 + l) * S_W, wq[l], DIM, HDH);
        tconv_kernel<<<tgrid, tblk>>>(wTH + (1 * 2 + l) * S_W, wTL + (1 * 2 + l) * S_W, wk[l], DIM, HDH);
        tconv_kernel<<<tgrid, tblk>>>(wTH + (2 * 2 + l) * S_W, wTL + (2 * 2 + l) * S_W, wv[l], DIM, HDH);
        tconv_kernel<<<dim3(DIM / 32, HDH / 32), tblk>>>(
            wTH + (3 * 2 + l) * S_W, wTL + (3 * 2 + l) * S_W, wo[l], HDH, DIM);
    }
    split_kernel<<<(Bc * Nq * DIM / 4 + 255) / 256, 256>>>(xH, xL, x, (long)Bc * Nq * DIM / 4);
    split_kernel<<<(2 * Bc * NCTX * DIM / 4 + 255) / 256, 256>>>(
        cH, cL, ctx, (long)2 * Bc * NCTX * DIM / 4);

    // ---- Q/K/V projections, both layers batched in z ----
    projk<<<dim3(8, 16, 2), 256, BIG_SMEM>>>(
        Bc * Nq, HDH, DIM, xH, xL, DIM, 0, wTH + 0 * S_W, wTL + 0 * S_W, DIM, S_W,
        qn, nullptr, (long)QN_L, nullptr, 0.0f, 1, Nq, Nq, 0);

    projk<<<dim3(8, 32, 2), 256, BIG_SMEM>>>(
        Bc * NCTX, HDH, DIM, cH, cL, DIM, (long)Bc * NCTX * DIM,
        wTH + 2 * S_W, wTL + 2 * S_W, DIM, S_W,
        kn, nullptr, (long)KN_L, nullptr, 0.0f, 1, NCTX, JJ, NMEM);

    projk<<<dim3(8, 32, 2), 256, BIG_SMEM>>>(
        Bc * NCTX, HDH, DIM, cH, cL, DIM, (long)Bc * NCTX * DIM,
        wTH + 4 * S_W, wTL + 4 * S_W, DIM, S_W,
        vTH, vTL, (long)VT_L, nullptr, 0.0f, 4, NCTX, 0, 0);

    memfill_kernel<<<64, 256>>>(kn, vTH, vTL, mk[0], mv[0], mk[1], mv[1]);

    l2norm_split_kernel<<<(2 * Bc * HH * Nq + 7) / 8, 256>>>(qn, qnH, qnL, 2 * Bc * HH * Nq);
    l2norm_split_kernel<<<(2 * Bc * HH * JJ + 7) / 8, 256>>>(kn, knH, knL, 2 * Bc * HH * JJ);

    // ---- dots, both layers: z = l*32 + b*16 + h ----
    dotsk<<<dim3(17, 8, 64), 256, BIG_SMEM>>>(
        Nq, JJ, DHH, qnH, qnL, DHH, (long)Nq * DHH,
        knH, knL, DHH, (long)JJ * DHH,
        dots, nullptr, (long)Nq * JJ, scl, 0.0f, 3, JJ, 0, 0);

    // ---- talking-heads mix + softmax, both layers ----
    mix_softmax_kernel<<<2 * Bc * Nq, 256, MIX_SMEM>>>(
        dots, atH, atL, thpre[0], thpost[0], thpre[1], thpost[1]);

    // ---- attn @ V, both layers: z = l*32 + b*16 + h ----
    avk<<<dim3(1, 16, 64), 128, SML_SMEM>>>(
        Nq, DHH, JJP, atH, atL, JJP, (long)Nq * JJP,
        vTH, vTL, JJP, (long)DHH * JJP,
        ctH, ctL, (long)CT_L, hsb, 0.0f, 2, Nq, 0, 0);

    // ---- output projection, both layers -> per-layer partials ----
    projk<<<dim3(8, 16, 2), 256, BIG_SMEM>>>(
        Bc * Nq, DIM, HDH, ctH, ctL, HDH, (long)CT_L,
        wTH + 6 * S_W, wTL + 6 * S_W, HDH, S_W,
        oacc, nullptr, (long)OA_L, nullptr, 0.0f, 3, DIM, 0, 0);

    // ---- out = oacc[0] + oacc[1] ----
    add_kernel<<<((int)(OA_L / 4) + 255) / 256, 256>>>(out, oacc, (long)OA_L / 4);
}

// round 17
// speedup vs baseline: 1.1695x; 1.0085x over previous
#include <cuda_runtime.h>
#include <cuda_bf16.h>
#include <math.h>
#include <stdint.h>

// Problem constants
#define HH 16
#define DHH 64
static constexpr int Bc   = 2;
static constexpr int Nq   = 1024;
static constexpr int NCTX = 2048;
static constexpr int DIM  = 1024;
static constexpr int NMEM = 16;
static constexpr int JJ   = NCTX + NMEM;   // 2064
static constexpr int JJP  = 2080;          // padded to multiple of 32 (BK)
static constexpr int HDH  = HH * DHH;      // 1024

// per-layer element counts
static constexpr size_t S_W    = (size_t)HDH * DIM;
static constexpr size_t QN_L   = (size_t)Bc * HH * Nq * DHH;
static constexpr size_t KN_L   = (size_t)Bc * HH * JJ * DHH;
static constexpr size_t VT_L   = (size_t)Bc * HH * DHH * JJP;
static constexpr size_t AT_L   = (size_t)Bc * HH * Nq * (size_t)JJP;
static constexpr size_t CT_L   = (size_t)Bc * Nq * HDH;
static constexpr size_t DOTS_L = (size_t)Bc * HH * Nq * (size_t)JJ;
static constexpr size_t OA_L   = (size_t)Bc * Nq * DIM;

// ---------------- scratch (device globals; both layers) ----------------------
__device__ float g_qn[2 * QN_L];
__device__ float g_kn[2 * KN_L];
__device__ float g_dots[2 * DOTS_L];
__device__ float g_oacc[2 * OA_L];
__device__ float g_scale[32];   // [l][h]
__device__ float g_hs[32];      // [l][h]

__device__ __align__(16) __nv_bfloat16 g_xH [(size_t)Bc * Nq * DIM];
__device__ __align__(16) __nv_bfloat16 g_xL [(size_t)Bc * Nq * DIM];
__device__ __align__(16) __nv_bfloat16 g_cH [2 * (size_t)Bc * NCTX * DIM];
__device__ __align__(16) __nv_bfloat16 g_cL [2 * (size_t)Bc * NCTX * DIM];
__device__ __align__(16) __nv_bfloat16 g_wTH[8 * S_W];   // q0,q1,k0,k1,v0,v1,o0,o1
__device__ __align__(16) __nv_bfloat16 g_wTL[8 * S_W];
__device__ __align__(16) __nv_bfloat16 g_qnH[2 * QN_L];
__device__ __align__(16) __nv_bfloat16 g_qnL[2 * QN_L];
__device__ __align__(16) __nv_bfloat16 g_knH[2 * KN_L];
__device__ __align__(16) __nv_bfloat16 g_knL[2 * KN_L];
__device__ __align__(16) __nv_bfloat16 g_vTH[2 * VT_L];
__device__ __align__(16) __nv_bfloat16 g_vTL[2 * VT_L];
__device__ __align__(16) __nv_bfloat16 g_atH[2 * AT_L];
__device__ __align__(16) __nv_bfloat16 g_atL[2 * AT_L];
__device__ __align__(16) __nv_bfloat16 g_ctH[2 * CT_L];
__device__ __align__(16) __nv_bfloat16 g_ctL[2 * CT_L];

// ---------------- split helpers ---------------------------------------------
__device__ __forceinline__ uint32_t pack_bf2(__nv_bfloat16 a, __nv_bfloat16 b) {
    return ((uint32_t)__bfloat16_as_ushort(b) << 16) | (uint32_t)__bfloat16_as_ushort(a);
}
__device__ __forceinline__ void split_bf16(float x, __nv_bfloat16& h, __nv_bfloat16& l) {
    h = __float2bfloat16(x);
    l = __float2bfloat16(x - __bfloat162float(h));
}

// ---------------- tiny kernels ----------------------------------------------

__global__ void prep_kernel(float* __restrict__ scl, float* __restrict__ hsb,
                            const float* __restrict__ p0, const float* __restrict__ p1,
                            const float* __restrict__ h0, const float* __restrict__ h1) {
    int t = threadIdx.x;
    int h = t & 15, l = t >> 4;
    const float* p = l ? p1 : p0;
    const float* hv = l ? h1 : h0;
    scl[t] = 1.0f / fmaxf(expf(p[h]), 0.01f);
    hsb[t] = hv[h];
}

__global__ void split_kernel(__nv_bfloat16* __restrict__ H, __nv_bfloat16* __restrict__ L,
                             const float* __restrict__ src, long n4) {
    long i = blockIdx.x * (long)blockDim.x + threadIdx.x;
    if (i >= n4) return;
    float4 v = reinterpret_cast<const float4*>(src)[i];
    __nv_bfloat16 h0,l0,h1,l1,h2,l2,h3,l3;
    split_bf16(v.x,h0,l0); split_bf16(v.y,h1,l1);
    split_bf16(v.z,h2,l2); split_bf16(v.w,h3,l3);
    reinterpret_cast<uint2*>(H)[i] = make_uint2(pack_bf2(h0,h1), pack_bf2(h2,h3));
    reinterpret_cast<uint2*>(L)[i] = make_uint2(pack_bf2(l0,l1), pack_bf2(l2,l3));
}

// all 8 weight transposes in one launch; every matrix is 1024x1024
struct W8 { const float* p[8]; };
__global__ void tconv_all_kernel(__nv_bfloat16* __restrict__ H, __nv_bfloat16* __restrict__ L,
                                 W8 w) {
    __shared__ float t[32][33];
    const int zi = blockIdx.z;
    const float* src = w.p[zi];
    __nv_bfloat16* Hd = H + (size_t)zi * S_W;
    __nv_bfloat16* Ld = L + (size_t)zi * S_W;
    int n0 = blockIdx.x * 32, k0 = blockIdx.y * 32;
    for (int yy = threadIdx.y; yy < 32; yy += 8)
        t[yy][threadIdx.x] = src[(long)(k0 + yy) * 1024 + n0 + threadIdx.x];
    __syncthreads();
    for (int yy = threadIdx.y; yy < 32; yy += 8) {
        float v = t[threadIdx.x][yy];
        long o = (long)(n0 + yy) * 1024 + k0 + threadIdx.x;
        __nv_bfloat16 h, l; split_bf16(v, h, l);
        Hd[o] = h; Ld[o] = l;
    }
}

__global__ void memfill_kernel(float* __restrict__ kn,
                               __nv_bfloat16* __restrict__ vTH, __nv_bfloat16* __restrict__ vTL,
                               const float* __restrict__ mk0, const float* __restrict__ mv0,
                               const float* __restrict__ mk1, const float* __restrict__ mv1) {
    int idx = blockIdx.x * blockDim.x + threadIdx.x;
    const int total = HH * NMEM * DHH;
    if (idx >= total) return;
    int h   = idx / (NMEM * DHH);
    int rem = idx % (NMEM * DHH);
    int m = rem / DHH, d = rem % DHH;
    for (int l = 0; l < 2; l++) {
        float k = (l ? mk1 : mk0)[idx];
        float v = (l ? mv1 : mv0)[idx];
        __nv_bfloat16 vh, vl; split_bf16(v, vh, vl);
        for (int b = 0; b < Bc; b++) {
            kn[(size_t)l * KN_L + (((size_t)(b * HH + h) * JJ) + m) * DHH + d] = k;
            size_t base = (size_t)l * VT_L + ((size_t)(b * HH + h) * DHH + d) * JJP;
            vTH[base + m] = vh;            vTL[base + m] = vl;
            vTH[base + JJ + m] = __float2bfloat16(0.f);
            vTL[base + JJ + m] = __float2bfloat16(0.f);
        }
    }
}

__global__ void l2norm_split_kernel(const float* __restrict__ src,
                                    __nv_bfloat16* __restrict__ H,
                                    __nv_bfloat16* __restrict__ L, int rows) {
    int row = blockIdx.x * 8 + (threadIdx.x >> 5);
    if (row >= rows) return;
    int lane = threadIdx.x & 31;
    float2 v = reinterpret_cast<const float2*>(src + (size_t)row * DHH)[lane];
    float ss = v.x * v.x + v.y * v.y;
    #pragma unroll
    for (int o = 16; o; o >>= 1) ss += __shfl_xor_sync(0xffffffffu, ss, o);
    float inv = 1.0f / fmaxf(sqrtf(ss), 1e-12f);
    __nv_bfloat16 hx,lx,hy,ly;
    split_bf16(v.x * inv, hx, lx);
    split_bf16(v.y * inv, hy, ly);
    reinterpret_cast<uint32_t*>(H)[(size_t)row * 32 + lane] = pack_bf2(hx, hy);
    reinterpret_cast<uint32_t*>(L)[(size_t)row * 32 + lane] = pack_bf2(lx, ly);
}

__global__ void add_kernel(float* __restrict__ out, const float* __restrict__ oa, long n4) {
    long i = blockIdx.x * (long)blockDim.x + threadIdx.x;
    if (i >= n4) return;
    float4 a = reinterpret_cast<const float4*>(oa)[i];
    float4 b = reinterpret_cast<const float4*>(oa + OA_L)[i];
    reinterpret_cast<float4*>(out)[i] =
        make_float4(a.x + b.x, a.y + b.y, a.z + b.z, a.w + b.w);
}

// ---------------- fused talking-heads pre-mix + softmax + post-mix ----------
__global__ void mix_softmax_kernel(const float* __restrict__ dots,
                                   __nv_bfloat16* __restrict__ atH,
                                   __nv_bfloat16* __restrict__ atL,
                                   const float* __restrict__ pre0,
                                   const float* __restrict__ post0,
                                   const float* __restrict__ pre1,
                                   const float* __restrict__ post1) {
    extern __shared__ float sh[];
    __shared__ float s_pre[HH * HH], s_post[HH * HH];
    __shared__ float red[HH][8];
    __shared__ float gmax[HH], gsum[HH], Mmat[HH * HH];

    const int l  = blockIdx.x / (Bc * Nq);
    const int bi = blockIdx.x % (Bc * Nq);
    const int b = bi / Nq, i = bi % Nq;
    const int tid = threadIdx.x;
    const int warp = tid >> 5, lane = tid & 31;

    const float* th_pre  = l ? pre1  : pre0;
    const float* th_post = l ? post1 : post0;
    dots += (size_t)l * DOTS_L;
    atH  += (size_t)l * AT_L;
    atL  += (size_t)l * AT_L;

    s_pre[tid]  = th_pre[tid];
    s_post[tid] = th_post[tid];

    for (int h = 0; h < HH; h++) {
        const float* src = dots + (((size_t)(b * HH + h) * Nq + i) * JJ);
        for (int j = tid; j < JJ; j += 256) sh[h * JJ + j] = src[j];
    }
    __syncthreads();

    float lmax[HH];
    #pragma unroll
    for (int g = 0; g < HH; g++) lmax[g] = -1e30f;
    for (int j = tid; j < JJ; j += 256) {
        float d[HH];
        #pragma unroll
        for (int h = 0; h < HH; h++) d[h] = sh[h * JJ + j];
        #pragma unroll
        for (int g = 0; g < HH; g++) {
            float m = 0.0f;
            #pragma unroll
            for (int h = 0; h < HH; h++) m = fmaf(s_pre[g * HH + h], d[h], m);
            sh[g * JJ + j] = m;
            lmax[g] = fmaxf(lmax[g], m);
        }
    }
    __syncthreads();
    #pragma unroll
    for (int g = 0; g < HH; g++) {
        float v = lmax[g];
        #pragma unroll
        for (int o = 16; o; o >>= 1) v = fmaxf(v, __shfl_xor_sync(0xffffffffu, v, o));
        if (lane == 0) red[g][warp] = v;
    }
    __syncthreads();
    if (tid < HH) {
        float v = red[tid][0];
        #pragma unroll
        for (int w = 1; w < 8; w++) v = fmaxf(v, red[tid][w]);
        gmax[tid] = v;
    }
    __syncthreads();

    float lsum[HH];
    #pragma unroll
    for (int g = 0; g < HH; g++) lsum[g] = 0.0f;
    for (int j = tid; j < JJ; j += 256) {
        #pragma unroll
        for (int g = 0; g < HH; g++) {
            float e = __expf(sh[g * JJ + j] - gmax[g]);
            sh[g * JJ + j] = e;
            lsum[g] += e;
        }
    }
    __syncthreads();
    #pragma unroll
    for (int g = 0; g < HH; g++) {
        float v = lsum[g];
        #pragma unroll
        for (int o = 16; o; o >>= 1) v += __shfl_xor_sync(0xffffffffu, v, o);
        if (lane == 0) red[g][warp] = v;
    }
    __syncthreads();
    if (tid < HH) {
        float v = 0.0f;
        #pragma unroll
        for (int w = 0; w < 8; w++) v += red[tid][w];
        gsum[tid] = v;
    }
    __syncthreads();
    Mmat[tid] = s_post[tid] / gsum[tid & 15];
    __syncthreads();

    for (int j = tid; j < JJP; j += 256) {
        float e[HH];
        bool in = (j < JJ);
        #pragma unroll
        for (int h = 0; h < HH; h++) e[h] = in ? sh[h * JJ + j] : 0.0f;
        #pragma unroll
        for (int g = 0; g < HH; g++) {
            float o = 0.0f;
            #pragma unroll
            for (int h = 0; h < HH; h++) o = fmaf(Mmat[g * HH + h], e[h], o);
            size_t oi = (((size_t)(b * HH + g) * Nq + i) * JJP) + j;
            __nv_bfloat16 oh, ol; split_bf16(o, oh, ol);
            atH[oi] = oh; atL[oi] = ol;
        }
    }
}

// ---------------- bf16x2 GEMM core: 3-stage cp.async + ldmatrix -------------

__device__ __forceinline__ void cp16(uint32_t dst, const void* src) {
    asm volatile("cp.async.ca.shared.global [%0], [%1], 16;" :: "r"(dst), "l"(src));
}
__device__ __forceinline__ void cpcommit() { asm volatile("cp.async.commit_group;"); }
template<int N> __device__ __forceinline__ void cpwait() {
    asm volatile("cp.async.wait_group %0;" :: "n"(N));
}

__device__ __forceinline__ void ldsm_x4(uint32_t& r0, uint32_t& r1, uint32_t& r2, uint32_t& r3,
                                        uint32_t addr) {
    asm volatile("ldmatrix.sync.aligned.m8n8.x4.shared.b16 {%0,%1,%2,%3}, [%4];"
                 : "=r"(r0), "=r"(r1), "=r"(r2), "=r"(r3) : "r"(addr));
}

__device__ __forceinline__ void mma_bf16(float* c, const uint32_t* a, const uint32_t* b) {
    asm volatile(
        "mma.sync.aligned.m16n8k16.row.col.f32.bf16.bf16.f32 "
        "{%0,%1,%2,%3}, {%4,%5,%6,%7}, {%8,%9}, {%0,%1,%2,%3};"
        : "+f"(c[0]), "+f"(c[1]), "+f"(c[2]), "+f"(c[3])
        : "r"(a[0]), "r"(a[1]), "r"(a[2]), "r"(a[3]),
          "r"(b[0]), "r"(b[1]));
}

template<int BM, int BN, int WM, int WN, bool GUARDN, int NTH>
__device__ __forceinline__ void gemm_core(
    int M, int Nc, int K,
    const __nv_bfloat16* __restrict__ Ah, const __nv_bfloat16* __restrict__ Al, long lda,
    const __nv_bfloat16* __restrict__ Bh, const __nv_bfloat16* __restrict__ Bl, long ldb,
    void* C0, void* C1, long sC, int z,
    const float* __restrict__ alphaVec, float beta, int mode,
    int p1, int p2, int p3, int rowBase, int colBase, uint32_t* smem)
{
    constexpr int BK  = 32;
    constexpr int PA  = BK / 2 + 4;
    constexpr int AW  = BM * PA;
    constexpr int BW  = BN * PA;
    constexpr int SW  = 2 * AW + 2 * BW;
    constexpr int MFR = WM / 16;
    constexpr int NFR = WN / 8;

    const uint32_t smem_addr = (uint32_t)__cvta_generic_to_shared(smem);
    const int tid  = threadIdx.x;
    const int warp = tid >> 5;
    const int lane = tid & 31;
    const int g    = lane >> 2;
    const int tg   = lane & 3;
    const int wr   = warp / (BN / WN);
    const int wc   = warp % (BN / WN);

    const int a_row  = (lane & 15);
    const int a_seg  = (lane >> 4) * 4;
    const int b_row  = (lane & 7) + ((lane >> 4) << 3);
    const int b_seg  = ((lane >> 3) & 1) * 4;

    float acc[MFR][NFR][4];
    #pragma unroll
    for (int i = 0; i < MFR; i++)
        #pragma unroll
        for (int j = 0; j < NFR; j++)
            #pragma unroll
            for (int q = 0; q < 4; q++) acc[i][j][q] = 0.0f;

    auto load_tile = [&](int stage, int k0) {
        uint32_t base = smem_addr + (uint32_t)stage * SW * 4;
        #pragma unroll 2
        for (int idx = tid; idx < BM * 4; idx += NTH) {
            int r  = idx >> 2;
            int c8 = idx & 3;
            long go = (long)(rowBase + r) * lda + k0 + c8 * 8;
            uint32_t d = base + (uint32_t)(r * PA + c8 * 4) * 4;
            cp16(d, Ah + go);
            cp16(d + AW * 4, Al + go);
        }
        #pragma unroll 2
        for (int idx = tid; idx < BN * 4; idx += NTH) {
            int c  = idx >> 2;
            int k8 = idx & 3;
            int gc = colBase + c;
            uint32_t d = base + (uint32_t)(2 * AW + c * PA + k8 * 4) * 4;
            if (!GUARDN || gc < Nc) {
                long go = (long)gc * ldb + k0 + k8 * 8;
                cp16(d, Bh + go);
                cp16(d + BW * 4, Bl + go);
            } else {
                uint4 zz = make_uint4(0, 0, 0, 0);
                *reinterpret_cast<uint4*>(&smem[stage * SW + 2 * AW + c * PA + k8 * 4]) = zz;
                *reinterpret_cast<uint4*>(&smem[stage * SW + 2 * AW + BW + c * PA + k8 * 4]) = zz;
            }
        }
    };

    const int nK = K / BK;
    load_tile(0, 0);
    cpcommit();
    if (nK > 1) { load_tile(1, BK); cpcommit(); }

    for (int kt = 0; kt < nK; kt++) {
        cpwait<1>();
        __syncthreads();
        if (kt + 2 < nK) load_tile((kt + 2) % 3, (kt + 2) * BK);
        cpcommit();

        int cur = kt % 3;
        uint32_t baseB = smem_addr + (uint32_t)cur * SW * 4;
        uint32_t aH = baseB;
        uint32_t aL = baseB + AW * 4;
        uint32_t bH = baseB + 2 * AW * 4;
        uint32_t bL = bH + BW * 4;

        #pragma unroll
        for (int kk = 0; kk < BK; kk += 16) {
            const int kp = kk / 2;
            uint32_t afH[MFR][4], afL[MFR][4];
            uint32_t bfH[NFR][2], bfL[NFR][2];
            #pragma unroll
            for (int mi = 0; mi < MFR; mi++) {
                uint32_t off = (uint32_t)((wr * WM + mi * 16 + a_row) * PA + kp + a_seg) * 4;
                ldsm_x4(afH[mi][0], afH[mi][1], afH[mi][2], afH[mi][3], aH + off);
                ldsm_x4(afL[mi][0], afL[mi][1], afL[mi][2], afL[mi][3], aL + off);
            }
            #pragma unroll
            for (int np = 0; np < NFR / 2; np++) {
                uint32_t off = (uint32_t)((wc * WN + np * 16 + b_row) * PA + kp + b_seg) * 4;
                ldsm_x4(bfH[2*np][0], bfH[2*np][1], bfH[2*np+1][0], bfH[2*np+1][1], bH + off);
                ldsm_x4(bfL[2*np][0], bfL[2*np][1], bfL[2*np+1][0], bfL[2*np+1][1], bL + off);
            }
            #pragma unroll
            for (int mi = 0; mi < MFR; mi++)
                #pragma unroll
                for (int ni = 0; ni < NFR; ni++) {
                    float* c = acc[mi][ni];
                    mma_bf16(c, afL[mi], bfH[ni]);
                    mma_bf16(c, afH[mi], bfL[ni]);
                    mma_bf16(c, afH[mi], bfH[ni]);
                }
        }
    }

    float alpha = 1.0f;
    if (alphaVec) alpha = alphaVec[((z >> 5) << 4) | (z & 15)];

    #pragma unroll
    for (int mi = 0; mi < MFR; mi++) {
        #pragma unroll
        for (int half = 0; half < 2; half++) {
            int gr = rowBase + wr * WM + mi * 16 + g + half * 8;
            if (gr >= M) continue;
            #pragma unroll
            for (int ni = 0; ni < NFR; ni++) {
                #pragma unroll
                for (int e = 0; e < 2; e++) {
                    int gc = colBase + wc * WN + ni * 8 + tg * 2 + e;
                    if (gc >= Nc) continue;
                    float val = alpha * acc[mi][ni][half * 2 + e];
                    if (mode == 0) {
                        float* cp = (float*)C0 + (long)z * sC + (long)gr * p1 + gc;
                        *cp = (beta == 0.0f) ? val : fmaf(beta, *cp, val);
                    } else if (mode == 1) {               // split-heads fp32
                        int b = gr / p1;
                        int rr = gr - b * p1;
                        int h = gc >> 6, d = gc & 63;
                        ((float*)C0)[(long)z * sC +
                            (((long)(b * HH + h) * p2 + p3 + rr) << 6) + d] = val;
                    } else if (mode == 2) {               // cat split bf16 (z=l*32+b*16+h)
                        int b = (z >> 4) & 1, h = z & 15;
                        long oi = (long)(z >> 5) * sC + (((long)(b * p1 + gr) * HH + h) << 6) + gc;
                        __nv_bfloat16 vh, vl; split_bf16(val, vh, vl);
                        ((__nv_bfloat16*)C0)[oi] = vh;
                        ((__nv_bfloat16*)C1)[oi] = vl;
                    } else if (mode == 3) {               // batched plain fp32
                        ((float*)C0)[(long)z * sC + (long)gr * p1 + gc] = val;
                    } else {                              // mode 4: vT split bf16
                        int b = gr / p1;
                        int rr = gr - b * p1;
                        int h = gc >> 6, d = gc & 63;
                        long oi = (long)z * sC +
                                  ((long)(b * HH + h) * DHH + d) * JJP + NMEM + rr;
                        __nv_bfloat16 vh, vl; split_bf16(val, vh, vl);
                        ((__nv_bfloat16*)C0)[oi] = vh;
                        ((__nv_bfloat16*)C1)[oi] = vl;
                    }
                }
            }
        }
    }
}

// ---------------- generic GEMM wrapper ---------------------------------------
template<int BM, int BN, int WM, int WN, bool GUARDN>
__global__ void __launch_bounds__((BM / WM) * (BN / WN) * 32)
psgemm_kernel(
    int M, int Nc, int K,
    const __nv_bfloat16* __restrict__ AH, const __nv_bfloat16* __restrict__ AL,
    long lda, long sA,
    const __nv_bfloat16* __restrict__ BH, const __nv_bfloat16* __restrict__ BL,
    long ldb, long sB,
    void* C0, void* C1, long sC,
    const float* __restrict__ alphaVec,
    float beta, int mode, int p1, int p2, int p3)
{
    extern __shared__ uint32_t smem[];
    const int z = blockIdx.z;
    gemm_core<BM, BN, WM, WN, GUARDN, (BM / WM) * (BN / WN) * 32>(
        M, Nc, K,
        AH + (long)z * sA, AL + (long)z * sA, lda,
        BH + (long)z * sB, BL + (long)z * sB, ldb,
        C0, C1, sC, z, alphaVec, beta, mode, p1, p2, p3,
        blockIdx.y * BM, blockIdx.x * BN, smem);
}

// ---------------- fused Q/K/V projection launch -------------------------------
// 1280 linear CTAs: [0,256)=Q (128/layer), [256,768)=K, [768,1280)=V
__global__ void __launch_bounds__(256)
qkv_kernel()
{
    extern __shared__ uint32_t smem[];
    int bid = blockIdx.x;
    int op, rem;
    if (bid < 256)      { op = 0; rem = bid; }
    else if (bid < 768) { op = 1; rem = bid - 256; }
    else                { op = 2; rem = bid - 768; }
    const int perL = (op == 0) ? 128 : 256;
    const int l  = rem / perL; rem -= l * perL;
    const int ty = rem >> 3;             // 16 or 32 row tiles
    const int tx = rem & 7;              // 8 col tiles

    const __nv_bfloat16* Ah = (op == 0) ? g_xH : g_cH + (size_t)l * Bc * NCTX * DIM;
    const __nv_bfloat16* Al = (op == 0) ? g_xL : g_cL + (size_t)l * Bc * NCTX * DIM;
    const __nv_bfloat16* Bh = g_wTH + (size_t)(op * 2 + l) * S_W;
    const __nv_bfloat16* Bl = g_wTL + (size_t)(op * 2 + l) * S_W;
    const int M = (op == 0) ? Bc * Nq : Bc * NCTX;

    void *C0, *C1 = nullptr;
    int mode, p1, p2, p3 = 0;
    if (op == 0)      { C0 = g_qn + l * QN_L; mode = 1; p1 = Nq;   p2 = Nq; }
    else if (op == 1) { C0 = g_kn + l * KN_L; mode = 1; p1 = NCTX; p2 = JJ; p3 = NMEM; }
    else              { C0 = g_vTH + l * VT_L; C1 = g_vTL + l * VT_L; mode = 4; p1 = NCTX; p2 = 0; }

    gemm_core<128, 128, 64, 32, false, 256>(
        M, HDH, DIM, Ah, Al, DIM, Bh, Bl, DIM,
        C0, C1, 0, 0, nullptr, 0.0f, mode, p1, p2, p3,
        ty * 128, tx * 128, smem);
}

// ---------------- host launch ------------------------------------------------

static constexpr size_t MIX_SMEM  = (size_t)HH * JJ * sizeof(float);        // 132096
static constexpr int    BIG_SMEM  = 3 * (2 * 128 * 20 + 2 * 128 * 20) * 4;  // 122880
static constexpr int    SML_SMEM  = 3 * (2 * 64 * 20 + 2 * 64 * 20) * 4;    // 61440

extern "C" void kernel_launch(void* const* d_in, const int* in_sizes, int n_in,
                              void* d_out, int out_size)
{
    (void)in_sizes; (void)n_in; (void)out_size;
    const float* x   = (const float*)d_in[0];
    const float* ctx = (const float*)d_in[1];
    const float* wq[2]     = {(const float*)d_in[2],  (const float*)d_in[5]};
    const float* wk[2]     = {(const float*)d_in[3],  (const float*)d_in[6]};
    const float* wv[2]     = {(const float*)d_in[4],  (const float*)d_in[7]};
    const float* thpre[2]  = {(const float*)d_in[8],  (const float*)d_in[10]};
    const float* thpost[2] = {(const float*)d_in[9],  (const float*)d_in[11]};
    const float* scp[2]    = {(const float*)d_in[12], (const float*)d_in[13]};
    const float* mk[2]     = {(const float*)d_in[14], (const float*)d_in[16]};
    const float* mv[2]     = {(const float*)d_in[15], (const float*)d_in[17]};
    const float* hs[2]     = {(const float*)d_in[18], (const float*)d_in[19]};
    const float* wo[2]     = {(const float*)d_in[20], (const float*)d_in[21]};
    float* out = (float*)d_out;

    float *qn, *kn, *dots, *scl, *hsb, *oacc;
    __nv_bfloat16 *xH,*xL,*cH,*cL,*wTH,*wTL,*qnH,*qnL,*knH,*knL,*vTH,*vTL,*atH,*atL,*ctH,*ctL;
    cudaGetSymbolAddress((void**)&qn,   g_qn);
    cudaGetSymbolAddress((void**)&kn,   g_kn);
    cudaGetSymbolAddress((void**)&dots, g_dots);
    cudaGetSymbolAddress((void**)&scl,  g_scale);
    cudaGetSymbolAddress((void**)&hsb,  g_hs);
    cudaGetSymbolAddress((void**)&oacc, g_oacc);
    cudaGetSymbolAddress((void**)&xH,  g_xH);  cudaGetSymbolAddress((void**)&xL,  g_xL);
    cudaGetSymbolAddress((void**)&cH,  g_cH);  cudaGetSymbolAddress((void**)&cL,  g_cL);
    cudaGetSymbolAddress((void**)&wTH, g_wTH); cudaGetSymbolAddress((void**)&wTL, g_wTL);
    cudaGetSymbolAddress((void**)&qnH, g_qnH); cudaGetSymbolAddress((void**)&qnL, g_qnL);
    cudaGetSymbolAddress((void**)&knH, g_knH); cudaGetSymbolAddress((void**)&knL, g_knL);
    cudaGetSymbolAddress((void**)&vTH, g_vTH); cudaGetSymbolAddress((void**)&vTL, g_vTL);
    cudaGetSymbolAddress((void**)&atH, g_atH); cudaGetSymbolAddress((void**)&atL, g_atL);
    cudaGetSymbolAddress((void**)&ctH, g_ctH); cudaGetSymbolAddress((void**)&ctL, g_ctL);

    auto dotsk = psgemm_kernel<128, 128, 64, 32, true>;
    auto avk   = psgemm_kernel<64, 64, 32, 16, false>;   // 8 warps now
    auto oprj  = psgemm_kernel<128, 128, 64, 32, false>;
    cudaFuncSetAttribute(qkv_kernel, cudaFuncAttributeMaxDynamicSharedMemorySize, BIG_SMEM);
    cudaFuncSetAttribute(dotsk, cudaFuncAttributeMaxDynamicSharedMemorySize, BIG_SMEM);
    cudaFuncSetAttribute(avk,   cudaFuncAttributeMaxDynamicSharedMemorySize, SML_SMEM);
    cudaFuncSetAttribute(oprj,  cudaFuncAttributeMaxDynamicSharedMemorySize, BIG_SMEM);
    cudaFuncSetAttribute(mix_softmax_kernel,
                         cudaFuncAttributeMaxDynamicSharedMemorySize, (int)MIX_SMEM);

    // 1: prep
    prep_kernel<<<1, 32>>>(scl, hsb, scp[0], scp[1], hs[0], hs[1]);

    // 2: all 8 weight transposes
    W8 w8;
    w8.p[0] = wq[0]; w8.p[1] = wq[1];
    w8.p[2] = wk[0]; w8.p[3] = wk[1];
    w8.p[4] = wv[0]; w8.p[5] = wv[1];
    w8.p[6] = wo[0]; w8.p[7] = wo[1];
    tconv_all_kernel<<<dim3(32, 32, 8), dim3(32, 8)>>>(wTH, wTL, w8);

    // 3-4: input splits
    split_kernel<<<(Bc * Nq * DIM / 4 + 255) / 256, 256>>>(xH, xL, x, (long)Bc * Nq * DIM / 4);
    split_kernel<<<(2 * Bc * NCTX * DIM / 4 + 255) / 256, 256>>>(
        cH, cL, ctx, (long)2 * Bc * NCTX * DIM / 4);

    // 5: memory tokens (rows [0,NMEM) of kn / cols [0,NMEM)+pad of vT — disjoint from qkv)
    memfill_kernel<<<64, 256>>>(kn, vTH, vTL, mk[0], mv[0], mk[1], mv[1]);

    // 6: fused Q/K/V projections, both layers (ncu -s 5 captures this)
    qkv_kernel<<<1280, 256, BIG_SMEM>>>();

    // 7-8: l2norm + split
    l2norm_split_kernel<<<(2 * Bc * HH * Nq + 7) / 8, 256>>>(qn, qnH, qnL, 2 * Bc * HH * Nq);
    l2norm_split_kernel<<<(2 * Bc * HH * JJ + 7) / 8, 256>>>(kn, knH, knL, 2 * Bc * HH * JJ);

    // 9: dots (z = l*32 + b*16 + h)
    dotsk<<<dim3(17, 8, 64), 256, BIG_SMEM>>>(
        Nq, JJ, DHH, qnH, qnL, DHH, (long)Nq * DHH,
        knH, knL, DHH, (long)JJ * DHH,
        dots, nullptr, (long)Nq * JJ, scl, 0.0f, 3, JJ, 0, 0);

    // 10: talking-heads mix + softmax
    mix_softmax_kernel<<<2 * Bc * Nq, 256, MIX_SMEM>>>(
        dots, atH, atL, thpre[0], thpost[0], thpre[1], thpost[1]);

    // 11: attn @ V (8-warp config)
    avk<<<dim3(1, 16, 64), 256, SML_SMEM>>>(
        Nq, DHH, JJP, atH, atL, JJP, (long)Nq * JJP,
        vTH, vTL, JJP, (long)DHH * JJP,
        ctH, ctL, (long)CT_L, hsb, 0.0f, 2, Nq, 0, 0);

    // 12: output projection -> per-layer partials
    oprj<<<dim3(8, 16, 2), 256, BIG_SMEM>>>(
        Bc * Nq, DIM, HDH, ctH, ctL, HDH, (long)CT_L,
        wTH + 6 * S_W, wTL + 6 * S_W, HDH, S_W,
        oacc, nullptr, (long)OA_L, nullptr, 0.0f, 3, DIM, 0, 0);

    // 13: out = oacc[0] + oacc[1]
    add_kernel<<<((int)(OA_L / 4) + 255) / 256, 256>>>(out, oacc, (long)OA_L / 4);
}